// round 1
// baseline (speedup 1.0000x reference)
#include <cuda_runtime.h>
#include <math.h>

#define B_  64
#define Hdim 28
#define Wdim 28
#define C_  384
#define G_  7
#define N_  49
#define NH_ 12
#define HD_ 32
#define NTOK (B_*Hdim*Wdim)          // 50176
#define NWIN (B_*16)                 // 1024
#define SCALE_ 0.17677669529663689f
#define EPS_ 1e-5f
#define MH_ (4*C_)                   // 1536

// ---------------- scratch (device globals; no allocation allowed) ----------------
__device__ float g_hwin[(size_t)NTOK * C_];        // LN1 output, window order
__device__ float g_qkv[(size_t)NTOK * 3 * C_];     // qkv, window order
__device__ float g_bias[NH_ * N_ * N_];            // position bias [h][i][j]
__device__ float g_attn[(size_t)NTOK * C_];        // attention out, window order
__device__ float g_x1[(size_t)NTOK * C_];          // x + proj (original order)
__device__ float g_h2[(size_t)NTOK * C_];          // LN2 output
__device__ float g_mlp[(size_t)NTOK * MH_];        // gelu(fc1) output

// ---------------- dynamic position bias ----------------
__device__ __forceinline__ void dpb_layer(const float* v, const float* g, const float* b,
                                          const float* w, const float* bias,
                                          float* out, int outdim) {
    float m = 0.f;
    #pragma unroll
    for (int j = 0; j < 24; j++) m += v[j];
    m *= (1.f / 24.f);
    float var = 0.f;
    #pragma unroll
    for (int j = 0; j < 24; j++) { float d = v[j] - m; var += d * d; }
    var *= (1.f / 24.f);
    float inv = rsqrtf(var + EPS_);
    float t[24];
    #pragma unroll
    for (int j = 0; j < 24; j++)
        t[j] = fmaxf((v[j] - m) * inv * g[j] + b[j], 0.f);
    for (int o = 0; o < outdim; o++) {
        float s = bias[o];
        #pragma unroll
        for (int i = 0; i < 24; i++) s += t[i] * w[i * outdim + o];
        out[o] = s;
    }
}

__global__ void pos_bias_kernel(const float* __restrict__ ppw, const float* __restrict__ ppb,
                                const float* __restrict__ l1g, const float* __restrict__ l1b,
                                const float* __restrict__ p1w, const float* __restrict__ p1b,
                                const float* __restrict__ l2g, const float* __restrict__ l2b,
                                const float* __restrict__ p2w, const float* __restrict__ p2b,
                                const float* __restrict__ l3g, const float* __restrict__ l3b,
                                const float* __restrict__ p3w, const float* __restrict__ p3b) {
    __shared__ float pos[169 * NH_];
    int tid = threadIdx.x;
    if (tid < 169) {
        float dh = (float)(tid / 13 - 6);
        float dw = (float)(tid % 13 - 6);
        float v[24], v2[24];
        #pragma unroll
        for (int j = 0; j < 24; j++)
            v[j] = dh * ppw[j] + dw * ppw[24 + j] + ppb[j];
        dpb_layer(v, l1g, l1b, p1w, p1b, v2, 24);
        dpb_layer(v2, l2g, l2b, p2w, p2b, v, 24);
        float out12[NH_];
        dpb_layer(v, l3g, l3b, p3w, p3b, out12, NH_);
        #pragma unroll
        for (int h = 0; h < NH_; h++) pos[tid * NH_ + h] = out12[h];
    }
    __syncthreads();
    for (int e = tid; e < NH_ * N_ * N_; e += blockDim.x) {
        int h = e / (N_ * N_);
        int rem = e % (N_ * N_);
        int i = rem / N_, j = rem % N_;
        int idx = (i / G_ - j / G_ + G_ - 1) * (2 * G_ - 1) + (i % G_ - j % G_ + G_ - 1);
        g_bias[e] = pos[idx * NH_ + h];
    }
}

// ---------------- layernorm (optionally fused window-partition permute) ----------------
template<bool PERM>
__global__ void ln_kernel(const float* __restrict__ x, const float* __restrict__ g,
                          const float* __restrict__ b, float* __restrict__ out) {
    int t = blockIdx.x;
    const float* xr = x + (size_t)t * C_;
    int tid = threadIdx.x;
    float vals[3];
    float s = 0.f, s2 = 0.f;
    #pragma unroll
    for (int u = 0; u < 3; u++) {
        float v = xr[tid + u * 128];
        vals[u] = v; s += v; s2 += v * v;
    }
    #pragma unroll
    for (int o = 16; o; o >>= 1) {
        s  += __shfl_down_sync(0xffffffffu, s, o);
        s2 += __shfl_down_sync(0xffffffffu, s2, o);
    }
    __shared__ float shs[4], shs2[4], shm[2];
    int wid = tid >> 5, lane = tid & 31;
    if (lane == 0) { shs[wid] = s; shs2[wid] = s2; }
    __syncthreads();
    if (tid == 0) {
        float ts = shs[0] + shs[1] + shs[2] + shs[3];
        float t2 = shs2[0] + shs2[1] + shs2[2] + shs2[3];
        float mean = ts * (1.f / C_);
        float var = t2 * (1.f / C_) - mean * mean;
        shm[0] = mean;
        shm[1] = rsqrtf(var + EPS_);
    }
    __syncthreads();
    float mean = shm[0], inv = shm[1];
    float* orow;
    if (PERM) {
        int bb = t / (Hdim * Wdim);
        int rr = t % (Hdim * Wdim);
        int hh = rr / Wdim, ww = rr % Wdim;
        int w = bb * 16 + (hh / G_) * 4 + (ww / G_);
        int p = (hh % G_) * G_ + (ww % G_);
        orow = out + ((size_t)w * N_ + p) * C_;
    } else {
        orow = out + (size_t)t * C_;
    }
    #pragma unroll
    for (int u = 0; u < 3; u++) {
        int i = tid + u * 128;
        orow[i] = (vals[u] - mean) * inv * g[i] + b[i];
    }
}

// ---------------- tiled fp32 GEMM: C[M,Nc] = A[M,K] @ B[K,Nc] + bias, epilogue by MODE ----
// MODE 0: plain (+bias)                     -> C[row*Nc+col]
// MODE 1: proj: +bias, +residual x (orig order), reverse-window scatter -> C[orig*384+col]
// MODE 2: fc1: +bias, exact gelu            -> C[row*Nc+col]
// MODE 3: fc2: +bias, +residual res (same order) -> C[row*Nc+col]
template<int MODE>
__global__ void gemm64(const float* __restrict__ A, const float* __restrict__ Bm,
                       const float* __restrict__ bias, float* __restrict__ C,
                       const float* __restrict__ res, int M, int K, int Nc) {
    __shared__ float As[16][72];
    __shared__ float Bs[16][64];
    int m0 = blockIdx.y * 64, n0 = blockIdx.x * 64;
    int tid = threadIdx.x;
    int tx = tid & 15, ty = tid >> 4;
    float acc[4][4] = {};

    int la_row = tid >> 2;          // 0..63
    int la_k = (tid & 3) * 4;       // 0,4,8,12
    int lb_row = tid >> 4;          // 0..15
    int lb_col = (tid & 15) * 4;    // 0..60

    for (int k0 = 0; k0 < K; k0 += 16) {
        float4 a4 = *(const float4*)&A[(size_t)(m0 + la_row) * K + k0 + la_k];
        As[la_k + 0][la_row] = a4.x;
        As[la_k + 1][la_row] = a4.y;
        As[la_k + 2][la_row] = a4.z;
        As[la_k + 3][la_row] = a4.w;
        *(float4*)&Bs[lb_row][lb_col] =
            *(const float4*)&Bm[(size_t)(k0 + lb_row) * Nc + n0 + lb_col];
        __syncthreads();
        #pragma unroll
        for (int k = 0; k < 16; k++) {
            float4 ra = *(const float4*)&As[k][ty * 4];
            float4 rb = *(const float4*)&Bs[k][tx * 4];
            float raa[4] = {ra.x, ra.y, ra.z, ra.w};
            float rbb[4] = {rb.x, rb.y, rb.z, rb.w};
            #pragma unroll
            for (int a = 0; a < 4; a++)
                #pragma unroll
                for (int b = 0; b < 4; b++)
                    acc[a][b] = fmaf(raa[a], rbb[b], acc[a][b]);
        }
        __syncthreads();
    }

    int col0 = n0 + tx * 4;
    float4 bia = *(const float4*)&bias[col0];
    float bb4[4] = {bia.x, bia.y, bia.z, bia.w};
    #pragma unroll
    for (int a = 0; a < 4; a++) {
        int row = m0 + ty * 4 + a;
        float v[4];
        #pragma unroll
        for (int b = 0; b < 4; b++) v[b] = acc[a][b] + bb4[b];
        if (MODE == 0) {
            *(float4*)&C[(size_t)row * Nc + col0] = make_float4(v[0], v[1], v[2], v[3]);
        } else if (MODE == 1) {
            int w = row / N_, p = row % N_;
            int bbi = w >> 4, wi = w & 15;
            int hh = (wi >> 2) * G_ + p / G_;
            int ww = (wi & 3) * G_ + p % G_;
            int orig = bbi * (Hdim * Wdim) + hh * Wdim + ww;
            float4 r4 = *(const float4*)&res[(size_t)orig * C_ + col0];
            *(float4*)&C[(size_t)orig * C_ + col0] =
                make_float4(v[0] + r4.x, v[1] + r4.y, v[2] + r4.z, v[3] + r4.w);
        } else if (MODE == 2) {
            #pragma unroll
            for (int b = 0; b < 4; b++)
                v[b] = 0.5f * v[b] * (1.f + erff(v[b] * 0.70710678118654752f));
            *(float4*)&C[(size_t)row * Nc + col0] = make_float4(v[0], v[1], v[2], v[3]);
        } else {
            float4 r4 = *(const float4*)&res[(size_t)row * Nc + col0];
            *(float4*)&C[(size_t)row * Nc + col0] =
                make_float4(v[0] + r4.x, v[1] + r4.y, v[2] + r4.z, v[3] + r4.w);
        }
    }
}

// ---------------- attention: one block per (window, head) ----------------
__global__ void attn_kernel(const float* __restrict__ qkv, float* __restrict__ out) {
    __shared__ float qs[N_ * 32];
    __shared__ float ks[N_ * 33];
    __shared__ float vs[N_ * 32];
    __shared__ float S[N_ * 50];
    int w = blockIdx.x / NH_;
    int h = blockIdx.x % NH_;
    const float* base = qkv + (size_t)w * N_ * (3 * C_) + h * HD_;
    for (int e = threadIdx.x; e < N_ * 32; e += blockDim.x) {
        int i = e >> 5, d = e & 31;
        const float* row = base + (size_t)i * (3 * C_);
        qs[e] = row[d] * SCALE_;
        ks[i * 33 + d] = row[C_ + d];
        vs[e] = row[2 * C_ + d];
    }
    __syncthreads();
    const float* bh = g_bias + h * N_ * N_;
    for (int e = threadIdx.x; e < N_ * N_; e += blockDim.x) {
        int i = e / N_, j = e % N_;
        float acc = bh[e];
        const float* qi = qs + i * 32;
        const float* kj = ks + j * 33;
        #pragma unroll
        for (int d = 0; d < 32; d++) acc = fmaf(qi[d], kj[d], acc);
        S[i * 50 + j] = acc;
    }
    __syncthreads();
    if (threadIdx.x < N_) {
        float* row = S + threadIdx.x * 50;
        float mx = row[0];
        #pragma unroll
        for (int j = 1; j < N_; j++) mx = fmaxf(mx, row[j]);
        float sum = 0.f;
        #pragma unroll
        for (int j = 0; j < N_; j++) { float e = __expf(row[j] - mx); row[j] = e; sum += e; }
        float inv = 1.f / sum;
        #pragma unroll
        for (int j = 0; j < N_; j++) row[j] *= inv;
    }
    __syncthreads();
    float* orow = out + (size_t)w * N_ * C_ + h * HD_;
    for (int e = threadIdx.x; e < N_ * 32; e += blockDim.x) {
        int i = e >> 5, d = e & 31;
        float acc = 0.f;
        const float* Pr = S + i * 50;
        #pragma unroll
        for (int j = 0; j < N_; j++) acc = fmaf(Pr[j], vs[j * 32 + d], acc);
        orow[(size_t)i * C_ + d] = acc;
    }
}

// ---------------- launch ----------------
extern "C" void kernel_launch(void* const* d_in, const int* in_sizes, int n_in,
                              void* d_out, int out_size) {
    const float* x       = (const float*)d_in[0];
    const float* norm1_g = (const float*)d_in[1];
    const float* norm1_b = (const float*)d_in[2];
    const float* qkv_w   = (const float*)d_in[3];
    const float* qkv_b   = (const float*)d_in[4];
    const float* proj_w  = (const float*)d_in[5];
    const float* proj_b  = (const float*)d_in[6];
    const float* norm2_g = (const float*)d_in[7];
    const float* norm2_b = (const float*)d_in[8];
    const float* fc1_w   = (const float*)d_in[9];
    const float* fc1_b   = (const float*)d_in[10];
    const float* fc2_w   = (const float*)d_in[11];
    const float* fc2_b   = (const float*)d_in[12];
    const float* pp_w    = (const float*)d_in[13];
    const float* pp_b    = (const float*)d_in[14];
    const float* l1_g    = (const float*)d_in[15];
    const float* l1_b    = (const float*)d_in[16];
    const float* p1_w    = (const float*)d_in[17];
    const float* p1_b    = (const float*)d_in[18];
    const float* l2_g    = (const float*)d_in[19];
    const float* l2_b    = (const float*)d_in[20];
    const float* p2_w    = (const float*)d_in[21];
    const float* p2_b    = (const float*)d_in[22];
    const float* l3_g    = (const float*)d_in[23];
    const float* l3_b    = (const float*)d_in[24];
    const float* p3_w    = (const float*)d_in[25];
    const float* p3_b    = (const float*)d_in[26];
    float* out = (float*)d_out;

    float *hwin, *qkvb, *attn, *x1, *h2, *mlp;
    cudaGetSymbolAddress((void**)&hwin, g_hwin);
    cudaGetSymbolAddress((void**)&qkvb, g_qkv);
    cudaGetSymbolAddress((void**)&attn, g_attn);
    cudaGetSymbolAddress((void**)&x1,   g_x1);
    cudaGetSymbolAddress((void**)&h2,   g_h2);
    cudaGetSymbolAddress((void**)&mlp,  g_mlp);

    // 1. dynamic position bias table
    pos_bias_kernel<<<1, 256>>>(pp_w, pp_b, l1_g, l1_b, p1_w, p1_b,
                                l2_g, l2_b, p2_w, p2_b, l3_g, l3_b, p3_w, p3_b);
    // 2. LN1 + window partition
    ln_kernel<true><<<NTOK, 128>>>(x, norm1_g, norm1_b, hwin);
    // 3. QKV GEMM  [50176,384] x [384,1152]
    gemm64<0><<<dim3(18, 784), 256>>>(hwin, qkv_w, qkv_b, qkvb, nullptr, NTOK, C_, 3 * C_);
    // 4. attention per (window, head)
    attn_kernel<<<NWIN * NH_, 256>>>(qkvb, attn);
    // 5. proj GEMM + residual + reverse window  [50176,384] x [384,384]
    gemm64<1><<<dim3(6, 784), 256>>>(attn, proj_w, proj_b, x1, x, NTOK, C_, C_);
    // 6. LN2
    ln_kernel<false><<<NTOK, 128>>>(x1, norm2_g, norm2_b, h2);
    // 7. FC1 GEMM + gelu  [50176,384] x [384,1536]
    gemm64<2><<<dim3(24, 784), 256>>>(h2, fc1_w, fc1_b, mlp, nullptr, NTOK, C_, MH_);
    // 8. FC2 GEMM + residual -> out  [50176,1536] x [1536,384]
    gemm64<3><<<dim3(6, 784), 256>>>(mlp, fc2_w, fc2_b, out, x1, NTOK, MH_, C_);
}

// round 9
// speedup vs baseline: 3.3155x; 3.3155x over previous
#include <cuda_runtime.h>
#include <cstdint>
#include <math.h>

#define B_  64
#define Hdim 28
#define Wdim 28
#define C_  384
#define G_  7
#define N_  49
#define NH_ 12
#define HD_ 32
#define NTOK (B_*Hdim*Wdim)          // 50176
#define NWIN (B_*16)                 // 1024
#define SCALE_ 0.17677669529663689f
#define EPS_ 1e-5f
#define MH_ (4*C_)                   // 1536

// ---------------- scratch (device globals) ----------------
__device__ float g_hwin[(size_t)NTOK * C_];        // LN1 output (tf32-rounded), window order
__device__ float g_qkv[(size_t)NTOK * 3 * C_];     // qkv, window order
__device__ float g_bias[NH_ * N_ * N_];            // position bias [h][i][j]
__device__ float g_attn[(size_t)NTOK * C_];        // attention out (tf32-rounded), window order
__device__ float g_x1[(size_t)NTOK * C_];          // x + proj (original order, fp32)
__device__ float g_h2[(size_t)NTOK * C_];          // LN2 output (tf32-rounded)
__device__ float g_mlp[(size_t)NTOK * MH_];        // gelu(fc1) (tf32-rounded)
// tf32-rounded weight copies (same layout as originals: [K][N])
__device__ float g_qkvW[(size_t)C_ * 3 * C_];
__device__ float g_projW[(size_t)C_ * C_];
__device__ float g_fc1W[(size_t)C_ * MH_];
__device__ float g_fc2W[(size_t)MH_ * C_];

// ---------------- helpers ----------------
__device__ __forceinline__ float to_tf32(float v) {
    asm("cvt.rna.tf32.f32 %0, %1;" : "=f"(v) : "f"(v));
    return v;
}
__device__ __forceinline__ uint32_t smem_u32(const void* p) {
    uint32_t a;
    asm("{ .reg .u64 t; cvta.to.shared.u64 t, %1; cvt.u32.u64 %0, t; }" : "=r"(a) : "l"(p));
    return a;
}
__device__ __forceinline__ void cp16(uint32_t dst, const void* src) {
    asm volatile("cp.async.cg.shared.global [%0], [%1], 16;" :: "r"(dst), "l"(src));
}
#define CP_COMMIT() asm volatile("cp.async.commit_group;" ::: "memory")
#define CP_WAIT1()  asm volatile("cp.async.wait_group 1;" ::: "memory")
#define CP_WAIT0()  asm volatile("cp.async.wait_group 0;" ::: "memory")

__device__ __forceinline__ void mma_tf32(float* c, uint32_t a0, uint32_t a1, uint32_t a2,
                                         uint32_t a3, uint32_t b0, uint32_t b1) {
    asm volatile(
        "mma.sync.aligned.m16n8k8.row.col.f32.tf32.tf32.f32 "
        "{%0,%1,%2,%3}, {%4,%5,%6,%7}, {%8,%9}, {%0,%1,%2,%3};"
        : "+f"(c[0]), "+f"(c[1]), "+f"(c[2]), "+f"(c[3])
        : "r"(a0), "r"(a1), "r"(a2), "r"(a3), "r"(b0), "r"(b1));
}

// ---------------- tf32 rounding pass (weights) ----------------
__global__ void cvt_tf32_kernel(const float* __restrict__ in, float* __restrict__ out, int n) {
    int i = blockIdx.x * 256 + threadIdx.x;
    if (i < n) out[i] = to_tf32(in[i]);
}

// ---------------- dynamic position bias ----------------
__device__ __forceinline__ void dpb_layer(const float* v, const float* g, const float* b,
                                          const float* w, const float* bias,
                                          float* out, int outdim) {
    float m = 0.f;
    #pragma unroll
    for (int j = 0; j < 24; j++) m += v[j];
    m *= (1.f / 24.f);
    float var = 0.f;
    #pragma unroll
    for (int j = 0; j < 24; j++) { float d = v[j] - m; var += d * d; }
    var *= (1.f / 24.f);
    float inv = rsqrtf(var + EPS_);
    float t[24];
    #pragma unroll
    for (int j = 0; j < 24; j++)
        t[j] = fmaxf((v[j] - m) * inv * g[j] + b[j], 0.f);
    for (int o = 0; o < outdim; o++) {
        float s = bias[o];
        #pragma unroll
        for (int i = 0; i < 24; i++) s += t[i] * w[i * outdim + o];
        out[o] = s;
    }
}

__global__ void pos_bias_kernel(const float* __restrict__ ppw, const float* __restrict__ ppb,
                                const float* __restrict__ l1g, const float* __restrict__ l1b,
                                const float* __restrict__ p1w, const float* __restrict__ p1b,
                                const float* __restrict__ l2g, const float* __restrict__ l2b,
                                const float* __restrict__ p2w, const float* __restrict__ p2b,
                                const float* __restrict__ l3g, const float* __restrict__ l3b,
                                const float* __restrict__ p3w, const float* __restrict__ p3b) {
    __shared__ float pos[169 * NH_];
    int tid = threadIdx.x;
    if (tid < 169) {
        float dh = (float)(tid / 13 - 6);
        float dw = (float)(tid % 13 - 6);
        float v[24], v2[24];
        #pragma unroll
        for (int j = 0; j < 24; j++)
            v[j] = dh * ppw[j] + dw * ppw[24 + j] + ppb[j];
        dpb_layer(v, l1g, l1b, p1w, p1b, v2, 24);
        dpb_layer(v2, l2g, l2b, p2w, p2b, v, 24);
        float out12[NH_];
        dpb_layer(v, l3g, l3b, p3w, p3b, out12, NH_);
        #pragma unroll
        for (int h = 0; h < NH_; h++) pos[tid * NH_ + h] = out12[h];
    }
    __syncthreads();
    for (int e = tid; e < NH_ * N_ * N_; e += blockDim.x) {
        int h = e / (N_ * N_);
        int rem = e % (N_ * N_);
        int i = rem / N_, j = rem % N_;
        int idx = (i / G_ - j / G_ + G_ - 1) * (2 * G_ - 1) + (i % G_ - j % G_ + G_ - 1);
        g_bias[e] = pos[idx * NH_ + h];
    }
}

// ---------------- layernorm (optional window permute; tf32-rounded output) ----------------
template<bool PERM>
__global__ void ln_kernel(const float* __restrict__ x, const float* __restrict__ g,
                          const float* __restrict__ b, float* __restrict__ out) {
    int t = blockIdx.x;
    const float* xr = x + (size_t)t * C_;
    int tid = threadIdx.x;
    float vals[3];
    float s = 0.f, s2 = 0.f;
    #pragma unroll
    for (int u = 0; u < 3; u++) {
        float v = xr[tid + u * 128];
        vals[u] = v; s += v; s2 += v * v;
    }
    #pragma unroll
    for (int o = 16; o; o >>= 1) {
        s  += __shfl_down_sync(0xffffffffu, s, o);
        s2 += __shfl_down_sync(0xffffffffu, s2, o);
    }
    __shared__ float shs[4], shs2[4], shm[2];
    int wid = tid >> 5, lane = tid & 31;
    if (lane == 0) { shs[wid] = s; shs2[wid] = s2; }
    __syncthreads();
    if (tid == 0) {
        float ts = shs[0] + shs[1] + shs[2] + shs[3];
        float t2 = shs2[0] + shs2[1] + shs2[2] + shs2[3];
        float mean = ts * (1.f / C_);
        float var = t2 * (1.f / C_) - mean * mean;
        shm[0] = mean;
        shm[1] = rsqrtf(var + EPS_);
    }
    __syncthreads();
    float mean = shm[0], inv = shm[1];
    float* orow;
    if (PERM) {
        int bb = t / (Hdim * Wdim);
        int rr = t % (Hdim * Wdim);
        int hh = rr / Wdim, ww = rr % Wdim;
        int w = bb * 16 + (hh / G_) * 4 + (ww / G_);
        int p = (hh % G_) * G_ + (ww % G_);
        orow = out + ((size_t)w * N_ + p) * C_;
    } else {
        orow = out + (size_t)t * C_;
    }
    #pragma unroll
    for (int u = 0; u < 3; u++) {
        int i = tid + u * 128;
        orow[i] = to_tf32((vals[u] - mean) * inv * g[i] + b[i]);
    }
}

// ---------------- mma.sync tf32 GEMM ----------------
// C[M,Nc] = A[M,K] @ W[K,Nc] + bias, MODE epilogues.
// CTA tile 256x128x32, 8 warps as 4(m) x 2(n), warp tile 64x64.
#define APAD 36
#define BPAD 136
#define A_FL (256 * APAD)             // 9216
#define B_FL (32 * BPAD)              // 4352
#define SM_FLOATS (2 * (A_FL + B_FL)) // 27136
#define SM_BYTES (SM_FLOATS * 4)      // 108544

template<int MODE>
__global__ void __launch_bounds__(256, 1)
gemm_mma(const float* __restrict__ A, const float* __restrict__ W,
         const float* __restrict__ bias, float* __restrict__ C,
         const float* __restrict__ res, int K, int Nc) {
    extern __shared__ __align__(16) float sm[];
    const int tid = threadIdx.x;
    const int lane = tid & 31, wid = tid >> 5;
    const int warp_m = wid & 3, warp_n = wid >> 2;
    const int m0 = blockIdx.y * 256, n0 = blockIdx.x * 128;
    const int nk = K / 32;

    uint32_t sbase = smem_u32(sm);

    // async-load chunk kt into buffer buf
    auto load_chunk = [&](int kt, int buf) {
        int k0 = kt * 32;
        uint32_t sA = sbase + (buf ? A_FL * 4 : 0);
        uint32_t sB = sbase + (2 * A_FL + (buf ? B_FL : 0)) * 4;
        #pragma unroll
        for (int u = 0; u < 8; u++) {              // 8*256 = 2048 cp16 = 256 rows x 32 k
            int idx = u * 256 + tid;
            int row = idx >> 3, seg = idx & 7;
            cp16(sA + (row * APAD + seg * 4) * 4,
                 &A[(size_t)(m0 + row) * K + k0 + seg * 4]);
        }
        #pragma unroll
        for (int u = 0; u < 4; u++) {              // 4*256 = 1024 cp16 = 32 k x 128 n
            int idx = u * 256 + tid;
            int kr = idx >> 5, seg = idx & 31;
            cp16(sB + (kr * BPAD + seg * 4) * 4,
                 &W[(size_t)(k0 + kr) * Nc + n0 + seg * 4]);
        }
        CP_COMMIT();
    };

    float acc[4][8][4];
    #pragma unroll
    for (int i = 0; i < 4; i++)
        #pragma unroll
        for (int j = 0; j < 8; j++)
            #pragma unroll
            for (int q = 0; q < 4; q++) acc[i][j][q] = 0.f;

    load_chunk(0, 0);
    load_chunk(1, 1);

    const int r = lane >> 2, cc = lane & 3;

    for (int kt = 0; kt < nk; kt++) {
        if (kt + 1 < nk) CP_WAIT1(); else CP_WAIT0();
        __syncthreads();
        const float* As = sm + (kt & 1 ? A_FL : 0);
        const float* Bs = sm + 2 * A_FL + (kt & 1 ? B_FL : 0);
        #pragma unroll
        for (int ks = 0; ks < 4; ks++) {
            uint32_t af[4][4];
            #pragma unroll
            for (int mf = 0; mf < 4; mf++) {
                const float* ap = As + (warp_m * 64 + mf * 16 + r) * APAD + ks * 8 + cc;
                af[mf][0] = __float_as_uint(ap[0]);
                af[mf][1] = __float_as_uint(ap[8 * APAD]);
                af[mf][2] = __float_as_uint(ap[4]);
                af[mf][3] = __float_as_uint(ap[8 * APAD + 4]);
            }
            uint32_t bf[8][2];
            #pragma unroll
            for (int nf = 0; nf < 8; nf++) {
                const float* bp = Bs + (ks * 8 + cc) * BPAD + warp_n * 64 + nf * 8 + r;
                bf[nf][0] = __float_as_uint(bp[0]);
                bf[nf][1] = __float_as_uint(bp[4 * BPAD]);
            }
            #pragma unroll
            for (int mf = 0; mf < 4; mf++)
                #pragma unroll
                for (int nf = 0; nf < 8; nf++)
                    mma_tf32(acc[mf][nf], af[mf][0], af[mf][1], af[mf][2], af[mf][3],
                             bf[nf][0], bf[nf][1]);
        }
        __syncthreads();
        if (kt + 2 < nk) load_chunk(kt + 2, kt & 1);
    }

    // epilogue
    #pragma unroll
    for (int mf = 0; mf < 4; mf++) {
        #pragma unroll
        for (int half = 0; half < 2; half++) {
            int row = m0 + warp_m * 64 + mf * 16 + r + half * 8;
            int orow = row;
            if (MODE == 1) {
                int w = row / N_, p = row % N_;
                int bbi = w >> 4, wi = w & 15;
                int hh = (wi >> 2) * G_ + p / G_;
                int ww = (wi & 3) * G_ + p % G_;
                orow = bbi * (Hdim * Wdim) + hh * Wdim + ww;
            }
            #pragma unroll
            for (int nf = 0; nf < 8; nf++) {
                int col = n0 + warp_n * 64 + nf * 8 + cc * 2;
                float2 bi = *(const float2*)&bias[col];
                float v0 = acc[mf][nf][half * 2 + 0] + bi.x;
                float v1 = acc[mf][nf][half * 2 + 1] + bi.y;
                if (MODE == 2) {
                    v0 = to_tf32(0.5f * v0 * (1.f + erff(v0 * 0.70710678118654752f)));
                    v1 = to_tf32(0.5f * v1 * (1.f + erff(v1 * 0.70710678118654752f)));
                } else if (MODE == 1 || MODE == 3) {
                    float2 r2 = *(const float2*)&res[(size_t)orow * Nc + col];
                    v0 += r2.x; v1 += r2.y;
                }
                *(float2*)&C[(size_t)orow * Nc + col] = make_float2(v0, v1);
            }
        }
    }
}

// ---------------- attention: one block per (window, head), reg-resident rows ----------------
__global__ void __launch_bounds__(64) attn_kernel(const float* __restrict__ qkv,
                                                  float* __restrict__ out) {
    __shared__ float ks[N_ * 32];
    __shared__ float vs[N_ * 32];
    int w = blockIdx.x / NH_;
    int h = blockIdx.x % NH_;
    const float* base = qkv + (size_t)w * N_ * (3 * C_) + h * HD_;
    int tid = threadIdx.x;
    for (int e = tid; e < N_ * 8; e += 64) {
        int i = e >> 3, d4 = e & 7;
        *(float4*)&ks[i * 32 + d4 * 4] = *(const float4*)&base[(size_t)i * (3 * C_) + C_ + d4 * 4];
        *(float4*)&vs[i * 32 + d4 * 4] = *(const float4*)&base[(size_t)i * (3 * C_) + 2 * C_ + d4 * 4];
    }
    float q[32];
    if (tid < N_) {
        #pragma unroll
        for (int d4 = 0; d4 < 8; d4++) {
            float4 t = *(const float4*)&base[(size_t)tid * (3 * C_) + d4 * 4];
            q[d4*4+0] = t.x * SCALE_; q[d4*4+1] = t.y * SCALE_;
            q[d4*4+2] = t.z * SCALE_; q[d4*4+3] = t.w * SCALE_;
        }
    }
    __syncthreads();
    if (tid >= N_) return;

    const float* bh = g_bias + h * N_ * N_ + tid * N_;
    float S[N_];
    #pragma unroll
    for (int j = 0; j < N_; j++) {
        float acc = bh[j];
        const float4* kj = (const float4*)&ks[j * 32];
        #pragma unroll
        for (int d4 = 0; d4 < 8; d4++) {
            float4 kk = kj[d4];
            acc = fmaf(q[d4*4+0], kk.x, acc);
            acc = fmaf(q[d4*4+1], kk.y, acc);
            acc = fmaf(q[d4*4+2], kk.z, acc);
            acc = fmaf(q[d4*4+3], kk.w, acc);
        }
        S[j] = acc;
    }
    float mx = S[0];
    #pragma unroll
    for (int j = 1; j < N_; j++) mx = fmaxf(mx, S[j]);
    float sum = 0.f;
    #pragma unroll
    for (int j = 0; j < N_; j++) { S[j] = __expf(S[j] - mx); sum += S[j]; }
    float inv = 1.f / sum;
    float o[32];
    #pragma unroll
    for (int d = 0; d < 32; d++) o[d] = 0.f;
    #pragma unroll
    for (int j = 0; j < N_; j++) {
        float p = S[j];
        const float4* vj = (const float4*)&vs[j * 32];
        #pragma unroll
        for (int d4 = 0; d4 < 8; d4++) {
            float4 vv = vj[d4];
            o[d4*4+0] = fmaf(p, vv.x, o[d4*4+0]);
            o[d4*4+1] = fmaf(p, vv.y, o[d4*4+1]);
            o[d4*4+2] = fmaf(p, vv.z, o[d4*4+2]);
            o[d4*4+3] = fmaf(p, vv.w, o[d4*4+3]);
        }
    }
    float* orow = out + (size_t)w * N_ * C_ + (size_t)tid * C_ + h * HD_;
    #pragma unroll
    for (int d4 = 0; d4 < 8; d4++)
        *(float4*)&orow[d4 * 4] = make_float4(to_tf32(o[d4*4+0] * inv), to_tf32(o[d4*4+1] * inv),
                                              to_tf32(o[d4*4+2] * inv), to_tf32(o[d4*4+3] * inv));
}

// ---------------- launch ----------------
extern "C" void kernel_launch(void* const* d_in, const int* in_sizes, int n_in,
                              void* d_out, int out_size) {
    const float* x       = (const float*)d_in[0];
    const float* norm1_g = (const float*)d_in[1];
    const float* norm1_b = (const float*)d_in[2];
    const float* qkv_w   = (const float*)d_in[3];
    const float* qkv_b   = (const float*)d_in[4];
    const float* proj_w  = (const float*)d_in[5];
    const float* proj_b  = (const float*)d_in[6];
    const float* norm2_g = (const float*)d_in[7];
    const float* norm2_b = (const float*)d_in[8];
    const float* fc1_w   = (const float*)d_in[9];
    const float* fc1_b   = (const float*)d_in[10];
    const float* fc2_w   = (const float*)d_in[11];
    const float* fc2_b   = (const float*)d_in[12];
    const float* pp_w    = (const float*)d_in[13];
    const float* pp_b    = (const float*)d_in[14];
    const float* l1_g    = (const float*)d_in[15];
    const float* l1_b    = (const float*)d_in[16];
    const float* p1_w    = (const float*)d_in[17];
    const float* p1_b    = (const float*)d_in[18];
    const float* l2_g    = (const float*)d_in[19];
    const float* l2_b    = (const float*)d_in[20];
    const float* p2_w    = (const float*)d_in[21];
    const float* p2_b    = (const float*)d_in[22];
    const float* l3_g    = (const float*)d_in[23];
    const float* l3_b    = (const float*)d_in[24];
    const float* p3_w    = (const float*)d_in[25];
    const float* p3_b    = (const float*)d_in[26];
    float* out = (float*)d_out;

    float *hwin, *qkvb, *attn, *x1, *h2, *mlp;
    float *qkvW, *projW, *fc1W, *fc2W;
    cudaGetSymbolAddress((void**)&hwin, g_hwin);
    cudaGetSymbolAddress((void**)&qkvb, g_qkv);
    cudaGetSymbolAddress((void**)&attn, g_attn);
    cudaGetSymbolAddress((void**)&x1,   g_x1);
    cudaGetSymbolAddress((void**)&h2,   g_h2);
    cudaGetSymbolAddress((void**)&mlp,  g_mlp);
    cudaGetSymbolAddress((void**)&qkvW, g_qkvW);
    cudaGetSymbolAddress((void**)&projW, g_projW);
    cudaGetSymbolAddress((void**)&fc1W, g_fc1W);
    cudaGetSymbolAddress((void**)&fc2W, g_fc2W);

    cudaFuncSetAttribute(gemm_mma<0>, cudaFuncAttributeMaxDynamicSharedMemorySize, SM_BYTES);
    cudaFuncSetAttribute(gemm_mma<1>, cudaFuncAttributeMaxDynamicSharedMemorySize, SM_BYTES);
    cudaFuncSetAttribute(gemm_mma<2>, cudaFuncAttributeMaxDynamicSharedMemorySize, SM_BYTES);
    cudaFuncSetAttribute(gemm_mma<3>, cudaFuncAttributeMaxDynamicSharedMemorySize, SM_BYTES);

    // tf32-round the weights
    cvt_tf32_kernel<<<(C_*3*C_ + 255)/256, 256>>>(qkv_w, qkvW, C_*3*C_);
    cvt_tf32_kernel<<<(C_*C_   + 255)/256, 256>>>(proj_w, projW, C_*C_);
    cvt_tf32_kernel<<<(C_*MH_  + 255)/256, 256>>>(fc1_w, fc1W, C_*MH_);
    cvt_tf32_kernel<<<(MH_*C_  + 255)/256, 256>>>(fc2_w, fc2W, MH_*C_);

    pos_bias_kernel<<<1, 256>>>(pp_w, pp_b, l1_g, l1_b, p1_w, p1_b,
                                l2_g, l2_b, p2_w, p2_b, l3_g, l3_b, p3_w, p3_b);
    ln_kernel<true><<<NTOK, 128>>>(x, norm1_g, norm1_b, hwin);

    // QKV: [50176,384] x [384,1152]
    gemm_mma<0><<<dim3((3*C_)/128, NTOK/256), 256, SM_BYTES>>>(hwin, qkvW, qkv_b, qkvb, nullptr, C_, 3*C_);
    attn_kernel<<<NWIN * NH_, 64>>>(qkvb, attn);
    // proj + residual + reverse window: [50176,384] x [384,384]
    gemm_mma<1><<<dim3(C_/128, NTOK/256), 256, SM_BYTES>>>(attn, projW, proj_b, x1, x, C_, C_);
    ln_kernel<false><<<NTOK, 128>>>(x1, norm2_g, norm2_b, h2);
    // fc1 + gelu: [50176,384] x [384,1536]
    gemm_mma<2><<<dim3(MH_/128, NTOK/256), 256, SM_BYTES>>>(h2, fc1W, fc1_b, mlp, nullptr, C_, MH_);
    // fc2 + residual -> out: [50176,1536] x [1536,384]
    gemm_mma<3><<<dim3(C_/128, NTOK/256), 256, SM_BYTES>>>(mlp, fc2W, fc2_b, out, x1, MH_, C_);
}

// round 10
// speedup vs baseline: 4.9857x; 1.5037x over previous
#include <cuda_runtime.h>
#include <cuda_bf16.h>
#include <cstdint>
#include <math.h>

#define B_  64
#define Hdim 28
#define Wdim 28
#define C_  384
#define G_  7
#define N_  49
#define NH_ 12
#define HD_ 32
#define NTOK (B_*Hdim*Wdim)          // 50176
#define NWIN (B_*16)                 // 1024
#define SCALE_ 0.17677669529663689f
#define EPS_ 1e-5f
#define MH_ (4*C_)                   // 1536

typedef __nv_bfloat16 bf16;

// ---------------- scratch (device globals) ----------------
__device__ bf16  g_hwin[(size_t)NTOK * C_];        // LN1 out, window order
__device__ bf16  g_qkv[(size_t)NTOK * 3 * C_];     // qkv, window order
__device__ float g_bias[NH_ * N_ * N_];            // position bias [h][i][j]
__device__ bf16  g_attn[(size_t)NTOK * C_];        // attention out, window order
__device__ float g_x1[(size_t)NTOK * C_];          // x + proj (orig order, fp32)
__device__ bf16  g_h2[(size_t)NTOK * C_];          // LN2 out
__device__ bf16  g_mlp[(size_t)NTOK * MH_];        // gelu(fc1)
// bf16 transposed weights [N][K]
__device__ bf16 g_qkvWT[(size_t)(3*C_) * C_];
__device__ bf16 g_projWT[(size_t)C_ * C_];
__device__ bf16 g_fc1WT[(size_t)MH_ * C_];
__device__ bf16 g_fc2WT[(size_t)C_ * MH_];

// ---------------- helpers ----------------
__device__ __forceinline__ uint32_t smem_u32(const void* p) {
    uint32_t a;
    asm("{ .reg .u64 t; cvta.to.shared.u64 t, %1; cvt.u32.u64 %0, t; }" : "=r"(a) : "l"(p));
    return a;
}
__device__ __forceinline__ void cp16(uint32_t dst, const void* src) {
    asm volatile("cp.async.cg.shared.global [%0], [%1], 16;" :: "r"(dst), "l"(src));
}
#define CP_COMMIT() asm volatile("cp.async.commit_group;" ::: "memory")
#define CP_WAIT1()  asm volatile("cp.async.wait_group 1;" ::: "memory")
#define CP_WAIT0()  asm volatile("cp.async.wait_group 0;" ::: "memory")

__device__ __forceinline__ void mma_bf16(float* c, uint32_t a0, uint32_t a1, uint32_t a2,
                                         uint32_t a3, uint32_t b0, uint32_t b1) {
    asm volatile(
        "mma.sync.aligned.m16n8k16.row.col.f32.bf16.bf16.f32 "
        "{%0,%1,%2,%3}, {%4,%5,%6,%7}, {%8,%9}, {%0,%1,%2,%3};"
        : "+f"(c[0]), "+f"(c[1]), "+f"(c[2]), "+f"(c[3])
        : "r"(a0), "r"(a1), "r"(a2), "r"(a3), "r"(b0), "r"(b1));
}
__device__ __forceinline__ float bflo(uint32_t u) { return __uint_as_float(u << 16); }
__device__ __forceinline__ float bfhi(uint32_t u) { return __uint_as_float(u & 0xFFFF0000u); }

// ---------------- weight convert+transpose: fp32 [R][Cc] -> bf16 [Cc][R] ----------------
__global__ void transpose_cvt(const float* __restrict__ in, bf16* __restrict__ out,
                              int R, int Cc) {
    __shared__ float t[32][33];
    int bx = blockIdx.x * 32, by = blockIdx.y * 32;
    int x = bx + threadIdx.x;
    #pragma unroll
    for (int u = 0; u < 32; u += 8) {
        int y = by + threadIdx.y + u;
        t[threadIdx.y + u][threadIdx.x] = in[(size_t)y * Cc + x];
    }
    __syncthreads();
    x = by + threadIdx.x;
    #pragma unroll
    for (int u = 0; u < 32; u += 8) {
        int y = bx + threadIdx.y + u;
        out[(size_t)y * R + x] = __float2bfloat16_rn(t[threadIdx.x][threadIdx.y + u]);
    }
}

// ---------------- dynamic position bias ----------------
__device__ __forceinline__ void dpb_layer(const float* v, const float* g, const float* b,
                                          const float* w, const float* bias,
                                          float* out, int outdim) {
    float m = 0.f;
    #pragma unroll
    for (int j = 0; j < 24; j++) m += v[j];
    m *= (1.f / 24.f);
    float var = 0.f;
    #pragma unroll
    for (int j = 0; j < 24; j++) { float d = v[j] - m; var += d * d; }
    var *= (1.f / 24.f);
    float inv = rsqrtf(var + EPS_);
    float t[24];
    #pragma unroll
    for (int j = 0; j < 24; j++)
        t[j] = fmaxf((v[j] - m) * inv * g[j] + b[j], 0.f);
    for (int o = 0; o < outdim; o++) {
        float s = bias[o];
        #pragma unroll
        for (int i = 0; i < 24; i++) s += t[i] * w[i * outdim + o];
        out[o] = s;
    }
}

__global__ void pos_bias_kernel(const float* __restrict__ ppw, const float* __restrict__ ppb,
                                const float* __restrict__ l1g, const float* __restrict__ l1b,
                                const float* __restrict__ p1w, const float* __restrict__ p1b,
                                const float* __restrict__ l2g, const float* __restrict__ l2b,
                                const float* __restrict__ p2w, const float* __restrict__ p2b,
                                const float* __restrict__ l3g, const float* __restrict__ l3b,
                                const float* __restrict__ p3w, const float* __restrict__ p3b) {
    __shared__ float pos[169 * NH_];
    int tid = threadIdx.x;
    if (tid < 169) {
        float dh = (float)(tid / 13 - 6);
        float dw = (float)(tid % 13 - 6);
        float v[24], v2[24];
        #pragma unroll
        for (int j = 0; j < 24; j++)
            v[j] = dh * ppw[j] + dw * ppw[24 + j] + ppb[j];
        dpb_layer(v, l1g, l1b, p1w, p1b, v2, 24);
        dpb_layer(v2, l2g, l2b, p2w, p2b, v, 24);
        float out12[NH_];
        dpb_layer(v, l3g, l3b, p3w, p3b, out12, NH_);
        #pragma unroll
        for (int h = 0; h < NH_; h++) pos[tid * NH_ + h] = out12[h];
    }
    __syncthreads();
    for (int e = tid; e < NH_ * N_ * N_; e += blockDim.x) {
        int h = e / (N_ * N_);
        int rem = e % (N_ * N_);
        int i = rem / N_, j = rem % N_;
        int idx = (i / G_ - j / G_ + G_ - 1) * (2 * G_ - 1) + (i % G_ - j % G_ + G_ - 1);
        g_bias[e] = pos[idx * NH_ + h];
    }
}

// ---------------- layernorm (optional window permute; bf16 output) ----------------
template<bool PERM>
__global__ void ln_kernel(const float* __restrict__ x, const float* __restrict__ g,
                          const float* __restrict__ b, bf16* __restrict__ out) {
    int t = blockIdx.x;
    const float* xr = x + (size_t)t * C_;
    int tid = threadIdx.x;
    float vals[3];
    float s = 0.f, s2 = 0.f;
    #pragma unroll
    for (int u = 0; u < 3; u++) {
        float v = xr[tid + u * 128];
        vals[u] = v; s += v; s2 += v * v;
    }
    #pragma unroll
    for (int o = 16; o; o >>= 1) {
        s  += __shfl_down_sync(0xffffffffu, s, o);
        s2 += __shfl_down_sync(0xffffffffu, s2, o);
    }
    __shared__ float shs[4], shs2[4], shm[2];
    int wid = tid >> 5, lane = tid & 31;
    if (lane == 0) { shs[wid] = s; shs2[wid] = s2; }
    __syncthreads();
    if (tid == 0) {
        float ts = shs[0] + shs[1] + shs[2] + shs[3];
        float t2 = shs2[0] + shs2[1] + shs2[2] + shs2[3];
        float mean = ts * (1.f / C_);
        float var = t2 * (1.f / C_) - mean * mean;
        shm[0] = mean;
        shm[1] = rsqrtf(var + EPS_);
    }
    __syncthreads();
    float mean = shm[0], inv = shm[1];
    bf16* orow;
    if (PERM) {
        int bb = t / (Hdim * Wdim);
        int rr = t % (Hdim * Wdim);
        int hh = rr / Wdim, ww = rr % Wdim;
        int w = bb * 16 + (hh / G_) * 4 + (ww / G_);
        int p = (hh % G_) * G_ + (ww % G_);
        orow = out + ((size_t)w * N_ + p) * C_;
    } else {
        orow = out + (size_t)t * C_;
    }
    #pragma unroll
    for (int u = 0; u < 3; u++) {
        int i = tid + u * 128;
        orow[i] = __float2bfloat16_rn((vals[u] - mean) * inv * g[i] + b[i]);
    }
}

// ---------------- bf16 mma.sync GEMM ----------------
// C[M,Nc] = A[M,K] @ WT[Nc,K]^T + bias
// MODE 0: bf16 out          1: fp32 out, +res, window scatter
// MODE 2: bf16 out, gelu    3: fp32 out, +res
// CTA 256x128, k-chunk 64, 8 warps 4(m)x2(n), warp tile 64x64.
#define APAD 72
#define BPAD 72
#define A_BYTES (256 * APAD * 2)      // 36864
#define B_BYTES (128 * BPAD * 2)      // 18432
#define SM_BYTES (2 * (A_BYTES + B_BYTES))  // 110592

template<int MODE>
__global__ void __launch_bounds__(256, 1)
gemm_mma(const bf16* __restrict__ A, const bf16* __restrict__ WT,
         const float* __restrict__ bias, void* __restrict__ Cout,
         const float* __restrict__ res, int K, int Nc) {
    extern __shared__ __align__(16) char smem[];
    const int tid = threadIdx.x;
    const int lane = tid & 31, wid = tid >> 5;
    const int warp_m = wid & 3, warp_n = wid >> 2;
    const int m0 = blockIdx.y * 256, n0 = blockIdx.x * 128;
    const int nk = K / 64;

    uint32_t sbase = smem_u32(smem);

    auto load_chunk = [&](int kt, int buf) {
        int k0 = kt * 64;
        uint32_t sA = sbase + (buf ? A_BYTES : 0);
        uint32_t sB = sbase + 2 * A_BYTES + (buf ? B_BYTES : 0);
        #pragma unroll
        for (int u = 0; u < 8; u++) {              // 2048 cp16 = 256 rows x 64 k
            int idx = u * 256 + tid;
            int row = idx >> 3, seg = idx & 7;
            cp16(sA + (row * APAD + seg * 8) * 2,
                 &A[(size_t)(m0 + row) * K + k0 + seg * 8]);
        }
        #pragma unroll
        for (int u = 0; u < 4; u++) {              // 1024 cp16 = 128 n x 64 k
            int idx = u * 256 + tid;
            int row = idx >> 3, seg = idx & 7;
            cp16(sB + (row * BPAD + seg * 8) * 2,
                 &WT[(size_t)(n0 + row) * K + k0 + seg * 8]);
        }
        CP_COMMIT();
    };

    float acc[4][8][4];
    #pragma unroll
    for (int i = 0; i < 4; i++)
        #pragma unroll
        for (int j = 0; j < 8; j++)
            #pragma unroll
            for (int q = 0; q < 4; q++) acc[i][j][q] = 0.f;

    load_chunk(0, 0);
    load_chunk(1, 1);

    const int r = lane >> 2, cc = lane & 3;

    for (int kt = 0; kt < nk; kt++) {
        if (kt + 1 < nk) CP_WAIT1(); else CP_WAIT0();
        __syncthreads();
        const bf16* As = (const bf16*)(smem + (kt & 1 ? A_BYTES : 0));
        const bf16* Bs = (const bf16*)(smem + 2 * A_BYTES + (kt & 1 ? B_BYTES : 0));
        #pragma unroll
        for (int ks = 0; ks < 4; ks++) {           // 4 x k16 = 64
            uint32_t af[4][4];
            #pragma unroll
            for (int mf = 0; mf < 4; mf++) {
                const bf16* ap = As + (warp_m * 64 + mf * 16 + r) * APAD + ks * 16 + 2 * cc;
                af[mf][0] = *(const uint32_t*)(ap);
                af[mf][1] = *(const uint32_t*)(ap + 8 * APAD);
                af[mf][2] = *(const uint32_t*)(ap + 8);
                af[mf][3] = *(const uint32_t*)(ap + 8 * APAD + 8);
            }
            uint32_t bf[8][2];
            #pragma unroll
            for (int nf = 0; nf < 8; nf++) {
                const bf16* bp = Bs + (warp_n * 64 + nf * 8 + r) * BPAD + ks * 16 + 2 * cc;
                bf[nf][0] = *(const uint32_t*)(bp);
                bf[nf][1] = *(const uint32_t*)(bp + 8);
            }
            #pragma unroll
            for (int mf = 0; mf < 4; mf++)
                #pragma unroll
                for (int nf = 0; nf < 8; nf++)
                    mma_bf16(acc[mf][nf], af[mf][0], af[mf][1], af[mf][2], af[mf][3],
                             bf[nf][0], bf[nf][1]);
        }
        __syncthreads();
        if (kt + 2 < nk) load_chunk(kt + 2, kt & 1);
    }

    // epilogue
    #pragma unroll
    for (int mf = 0; mf < 4; mf++) {
        #pragma unroll
        for (int half = 0; half < 2; half++) {
            int row = m0 + warp_m * 64 + mf * 16 + r + half * 8;
            int orow = row;
            if (MODE == 1) {
                int w = row / N_, p = row % N_;
                int bbi = w >> 4, wi = w & 15;
                int hh = (wi >> 2) * G_ + p / G_;
                int ww = (wi & 3) * G_ + p % G_;
                orow = bbi * (Hdim * Wdim) + hh * Wdim + ww;
            }
            #pragma unroll
            for (int nf = 0; nf < 8; nf++) {
                int col = n0 + warp_n * 64 + nf * 8 + cc * 2;
                float2 bi = *(const float2*)&bias[col];
                float v0 = acc[mf][nf][half * 2 + 0] + bi.x;
                float v1 = acc[mf][nf][half * 2 + 1] + bi.y;
                if (MODE == 2) {
                    v0 = 0.5f * v0 * (1.f + erff(v0 * 0.70710678118654752f));
                    v1 = 0.5f * v1 * (1.f + erff(v1 * 0.70710678118654752f));
                }
                if (MODE == 1 || MODE == 3) {
                    float2 r2 = *(const float2*)&res[(size_t)orow * Nc + col];
                    v0 += r2.x; v1 += r2.y;
                    *(float2*)&((float*)Cout)[(size_t)orow * Nc + col] = make_float2(v0, v1);
                } else {
                    __nv_bfloat162 h2 = __floats2bfloat162_rn(v0, v1);
                    *(__nv_bfloat162*)&((bf16*)Cout)[(size_t)orow * Nc + col] = h2;
                }
            }
        }
    }
}

// ---------------- attention: one block per (window, head) ----------------
__global__ void __launch_bounds__(64) attn_kernel(const bf16* __restrict__ qkv,
                                                  bf16* __restrict__ out) {
    __shared__ float ks[N_ * 32];
    __shared__ float vs[N_ * 32];
    int w = blockIdx.x / NH_;
    int h = blockIdx.x % NH_;
    const bf16* base = qkv + (size_t)w * N_ * (3 * C_) + h * HD_;
    int tid = threadIdx.x;
    for (int e = tid; e < N_ * 4; e += 64) {
        int i = e >> 2, g = e & 3;
        uint4 ku = *(const uint4*)&base[(size_t)i * (3 * C_) + C_ + g * 8];
        uint4 vu = *(const uint4*)&base[(size_t)i * (3 * C_) + 2 * C_ + g * 8];
        float* kd = &ks[i * 32 + g * 8];
        float* vd = &vs[i * 32 + g * 8];
        kd[0] = bflo(ku.x); kd[1] = bfhi(ku.x); kd[2] = bflo(ku.y); kd[3] = bfhi(ku.y);
        kd[4] = bflo(ku.z); kd[5] = bfhi(ku.z); kd[6] = bflo(ku.w); kd[7] = bfhi(ku.w);
        vd[0] = bflo(vu.x); vd[1] = bfhi(vu.x); vd[2] = bflo(vu.y); vd[3] = bfhi(vu.y);
        vd[4] = bflo(vu.z); vd[5] = bfhi(vu.z); vd[6] = bflo(vu.w); vd[7] = bfhi(vu.w);
    }
    float q[32];
    if (tid < N_) {
        #pragma unroll
        for (int g = 0; g < 4; g++) {
            uint4 qu = *(const uint4*)&base[(size_t)tid * (3 * C_) + g * 8];
            float* qd = &q[g * 8];
            qd[0] = bflo(qu.x) * SCALE_; qd[1] = bfhi(qu.x) * SCALE_;
            qd[2] = bflo(qu.y) * SCALE_; qd[3] = bfhi(qu.y) * SCALE_;
            qd[4] = bflo(qu.z) * SCALE_; qd[5] = bfhi(qu.z) * SCALE_;
            qd[6] = bflo(qu.w) * SCALE_; qd[7] = bfhi(qu.w) * SCALE_;
        }
    }
    __syncthreads();
    if (tid >= N_) return;

    const float* bh = g_bias + h * N_ * N_ + tid * N_;
    float S[N_];
    #pragma unroll
    for (int j = 0; j < N_; j++) {
        float acc = bh[j];
        const float4* kj = (const float4*)&ks[j * 32];
        #pragma unroll
        for (int d4 = 0; d4 < 8; d4++) {
            float4 kk = kj[d4];
            acc = fmaf(q[d4*4+0], kk.x, acc);
            acc = fmaf(q[d4*4+1], kk.y, acc);
            acc = fmaf(q[d4*4+2], kk.z, acc);
            acc = fmaf(q[d4*4+3], kk.w, acc);
        }
        S[j] = acc;
    }
    float mx = S[0];
    #pragma unroll
    for (int j = 1; j < N_; j++) mx = fmaxf(mx, S[j]);
    float sum = 0.f;
    #pragma unroll
    for (int j = 0; j < N_; j++) { S[j] = __expf(S[j] - mx); sum += S[j]; }
    float inv = 1.f / sum;
    float o[32];
    #pragma unroll
    for (int d = 0; d < 32; d++) o[d] = 0.f;
    #pragma unroll
    for (int j = 0; j < N_; j++) {
        float p = S[j];
        const float4* vj = (const float4*)&vs[j * 32];
        #pragma unroll
        for (int d4 = 0; d4 < 8; d4++) {
            float4 vv = vj[d4];
            o[d4*4+0] = fmaf(p, vv.x, o[d4*4+0]);
            o[d4*4+1] = fmaf(p, vv.y, o[d4*4+1]);
            o[d4*4+2] = fmaf(p, vv.z, o[d4*4+2]);
            o[d4*4+3] = fmaf(p, vv.w, o[d4*4+3]);
        }
    }
    bf16* orow = out + (size_t)w * N_ * C_ + (size_t)tid * C_ + h * HD_;
    uint32_t st[16];
    #pragma unroll
    for (int p = 0; p < 16; p++) {
        __nv_bfloat162 h2 = __floats2bfloat162_rn(o[2*p] * inv, o[2*p+1] * inv);
        st[p] = *(uint32_t*)&h2;
    }
    #pragma unroll
    for (int g = 0; g < 4; g++)
        *(uint4*)&orow[g * 8] = make_uint4(st[4*g], st[4*g+1], st[4*g+2], st[4*g+3]);
}

// ---------------- launch ----------------
extern "C" void kernel_launch(void* const* d_in, const int* in_sizes, int n_in,
                              void* d_out, int out_size) {
    const float* x       = (const float*)d_in[0];
    const float* norm1_g = (const float*)d_in[1];
    const float* norm1_b = (const float*)d_in[2];
    const float* qkv_w   = (const float*)d_in[3];
    const float* qkv_b   = (const float*)d_in[4];
    const float* proj_w  = (const float*)d_in[5];
    const float* proj_b  = (const float*)d_in[6];
    const float* norm2_g = (const float*)d_in[7];
    const float* norm2_b = (const float*)d_in[8];
    const float* fc1_w   = (const float*)d_in[9];
    const float* fc1_b   = (const float*)d_in[10];
    const float* fc2_w   = (const float*)d_in[11];
    const float* fc2_b   = (const float*)d_in[12];
    const float* pp_w    = (const float*)d_in[13];
    const float* pp_b    = (const float*)d_in[14];
    const float* l1_g    = (const float*)d_in[15];
    const float* l1_b    = (const float*)d_in[16];
    const float* p1_w    = (const float*)d_in[17];
    const float* p1_b    = (const float*)d_in[18];
    const float* l2_g    = (const float*)d_in[19];
    const float* l2_b    = (const float*)d_in[20];
    const float* p2_w    = (const float*)d_in[21];
    const float* p2_b    = (const float*)d_in[22];
    const float* l3_g    = (const float*)d_in[23];
    const float* l3_b    = (const float*)d_in[24];
    const float* p3_w    = (const float*)d_in[25];
    const float* p3_b    = (const float*)d_in[26];
    float* out = (float*)d_out;

    bf16 *hwin, *qkvb, *attn, *h2, *mlp;
    float *x1;
    bf16 *qkvWT, *projWT, *fc1WT, *fc2WT;
    cudaGetSymbolAddress((void**)&hwin, g_hwin);
    cudaGetSymbolAddress((void**)&qkvb, g_qkv);
    cudaGetSymbolAddress((void**)&attn, g_attn);
    cudaGetSymbolAddress((void**)&x1,   g_x1);
    cudaGetSymbolAddress((void**)&h2,   g_h2);
    cudaGetSymbolAddress((void**)&mlp,  g_mlp);
    cudaGetSymbolAddress((void**)&qkvWT, g_qkvWT);
    cudaGetSymbolAddress((void**)&projWT, g_projWT);
    cudaGetSymbolAddress((void**)&fc1WT, g_fc1WT);
    cudaGetSymbolAddress((void**)&fc2WT, g_fc2WT);

    cudaFuncSetAttribute(gemm_mma<0>, cudaFuncAttributeMaxDynamicSharedMemorySize, SM_BYTES);
    cudaFuncSetAttribute(gemm_mma<1>, cudaFuncAttributeMaxDynamicSharedMemorySize, SM_BYTES);
    cudaFuncSetAttribute(gemm_mma<2>, cudaFuncAttributeMaxDynamicSharedMemorySize, SM_BYTES);
    cudaFuncSetAttribute(gemm_mma<3>, cudaFuncAttributeMaxDynamicSharedMemorySize, SM_BYTES);

    dim3 tt(32, 8);
    // weights: fp32 [K][N] -> bf16 [N][K]
    transpose_cvt<<<dim3((3*C_)/32, C_/32), tt>>>(qkv_w, qkvWT, C_, 3*C_);
    transpose_cvt<<<dim3(C_/32, C_/32), tt>>>(proj_w, projWT, C_, C_);
    transpose_cvt<<<dim3(MH_/32, C_/32), tt>>>(fc1_w, fc1WT, C_, MH_);
    transpose_cvt<<<dim3(C_/32, MH_/32), tt>>>(fc2_w, fc2WT, MH_, C_);

    pos_bias_kernel<<<1, 256>>>(pp_w, pp_b, l1_g, l1_b, p1_w, p1_b,
                                l2_g, l2_b, p2_w, p2_b, l3_g, l3_b, p3_w, p3_b);
    ln_kernel<true><<<NTOK, 128>>>(x, norm1_g, norm1_b, hwin);

    // QKV: [50176,384] x [384,1152]
    gemm_mma<0><<<dim3((3*C_)/128, NTOK/256), 256, SM_BYTES>>>(hwin, qkvWT, qkv_b, qkvb, nullptr, C_, 3*C_);
    attn_kernel<<<NWIN * NH_, 64>>>(qkvb, attn);
    // proj + residual + reverse window
    gemm_mma<1><<<dim3(C_/128, NTOK/256), 256, SM_BYTES>>>(attn, projWT, proj_b, x1, x, C_, C_);
    ln_kernel<false><<<NTOK, 128>>>(x1, norm2_g, norm2_b, h2);
    // fc1 + gelu
    gemm_mma<2><<<dim3(MH_/128, NTOK/256), 256, SM_BYTES>>>(h2, fc1WT, fc1_b, mlp, nullptr, C_, MH_);
    // fc2 + residual -> out
    gemm_mma<3><<<dim3(C_/128, NTOK/256), 256, SM_BYTES>>>(mlp, fc2WT, fc2_b, out, x1, MH_, C_);
}

// round 11
// speedup vs baseline: 5.0644x; 1.0158x over previous
#include <cuda_runtime.h>
#include <cuda_bf16.h>
#include <cstdint>
#include <math.h>

#define B_  64
#define Hdim 28
#define Wdim 28
#define C_  384
#define G_  7
#define N_  49
#define NH_ 12
#define HD_ 32
#define NTOK (B_*Hdim*Wdim)          // 50176
#define NWIN (B_*16)                 // 1024
#define SCALE_ 0.17677669529663689f
#define EPS_ 1e-5f
#define MH_ (4*C_)                   // 1536

typedef __nv_bfloat16 bf16;

// ---------------- scratch (device globals) ----------------
__device__ bf16  g_hwin[(size_t)NTOK * C_];        // LN1 out, window order
__device__ bf16  g_qkv[(size_t)NTOK * 3 * C_];     // qkv, window order
__device__ float g_bias[NH_ * N_ * N_];            // position bias [h][i][j]
__device__ bf16  g_attn[(size_t)NTOK * C_];        // attention out, window order
__device__ float g_x1[(size_t)NTOK * C_];          // x + proj (orig order, fp32)
__device__ bf16  g_h2[(size_t)NTOK * C_];          // LN2 out
__device__ bf16  g_mlp[(size_t)NTOK * MH_];        // gelu(fc1)
// bf16 transposed weights [N][K]
__device__ bf16 g_qkvWT[(size_t)(3*C_) * C_];
__device__ bf16 g_projWT[(size_t)C_ * C_];
__device__ bf16 g_fc1WT[(size_t)MH_ * C_];
__device__ bf16 g_fc2WT[(size_t)C_ * MH_];

// ---------------- helpers ----------------
__device__ __forceinline__ uint32_t smem_u32(const void* p) {
    uint32_t a;
    asm("{ .reg .u64 t; cvta.to.shared.u64 t, %1; cvt.u32.u64 %0, t; }" : "=r"(a) : "l"(p));
    return a;
}
__device__ __forceinline__ void cp16(uint32_t dst, const void* src) {
    asm volatile("cp.async.cg.shared.global [%0], [%1], 16;" :: "r"(dst), "l"(src));
}
#define CP_COMMIT() asm volatile("cp.async.commit_group;" ::: "memory")
#define CP_WAIT1()  asm volatile("cp.async.wait_group 1;" ::: "memory")
#define CP_WAIT0()  asm volatile("cp.async.wait_group 0;" ::: "memory")

__device__ __forceinline__ void mma_bf16(float* c, uint32_t a0, uint32_t a1, uint32_t a2,
                                         uint32_t a3, uint32_t b0, uint32_t b1) {
    asm volatile(
        "mma.sync.aligned.m16n8k16.row.col.f32.bf16.bf16.f32 "
        "{%0,%1,%2,%3}, {%4,%5,%6,%7}, {%8,%9}, {%0,%1,%2,%3};"
        : "+f"(c[0]), "+f"(c[1]), "+f"(c[2]), "+f"(c[3])
        : "r"(a0), "r"(a1), "r"(a2), "r"(a3), "r"(b0), "r"(b1));
}
__device__ __forceinline__ void ldsm4(uint32_t& d0, uint32_t& d1, uint32_t& d2, uint32_t& d3,
                                      uint32_t addr) {
    asm volatile("ldmatrix.sync.aligned.m8n8.x4.shared.b16 {%0,%1,%2,%3}, [%4];"
        : "=r"(d0), "=r"(d1), "=r"(d2), "=r"(d3) : "r"(addr));
}
__device__ __forceinline__ float bflo(uint32_t u) { return __uint_as_float(u << 16); }
__device__ __forceinline__ float bfhi(uint32_t u) { return __uint_as_float(u & 0xFFFF0000u); }

// ---------------- weight convert+transpose: fp32 [R][Cc] -> bf16 [Cc][R] ----------------
__global__ void transpose_cvt(const float* __restrict__ in, bf16* __restrict__ out,
                              int R, int Cc) {
    __shared__ float t[32][33];
    int bx = blockIdx.x * 32, by = blockIdx.y * 32;
    int x = bx + threadIdx.x;
    #pragma unroll
    for (int u = 0; u < 32; u += 8) {
        int y = by + threadIdx.y + u;
        t[threadIdx.y + u][threadIdx.x] = in[(size_t)y * Cc + x];
    }
    __syncthreads();
    x = by + threadIdx.x;
    #pragma unroll
    for (int u = 0; u < 32; u += 8) {
        int y = bx + threadIdx.y + u;
        out[(size_t)y * R + x] = __float2bfloat16_rn(t[threadIdx.x][threadIdx.y + u]);
    }
}

// ---------------- dynamic position bias ----------------
__device__ __forceinline__ void dpb_layer(const float* v, const float* g, const float* b,
                                          const float* w, const float* bias,
                                          float* out, int outdim) {
    float m = 0.f;
    #pragma unroll
    for (int j = 0; j < 24; j++) m += v[j];
    m *= (1.f / 24.f);
    float var = 0.f;
    #pragma unroll
    for (int j = 0; j < 24; j++) { float d = v[j] - m; var += d * d; }
    var *= (1.f / 24.f);
    float inv = rsqrtf(var + EPS_);
    float t[24];
    #pragma unroll
    for (int j = 0; j < 24; j++)
        t[j] = fmaxf((v[j] - m) * inv * g[j] + b[j], 0.f);
    for (int o = 0; o < outdim; o++) {
        float s = bias[o];
        #pragma unroll
        for (int i = 0; i < 24; i++) s += t[i] * w[i * outdim + o];
        out[o] = s;
    }
}

__global__ void pos_bias_kernel(const float* __restrict__ ppw, const float* __restrict__ ppb,
                                const float* __restrict__ l1g, const float* __restrict__ l1b,
                                const float* __restrict__ p1w, const float* __restrict__ p1b,
                                const float* __restrict__ l2g, const float* __restrict__ l2b,
                                const float* __restrict__ p2w, const float* __restrict__ p2b,
                                const float* __restrict__ l3g, const float* __restrict__ l3b,
                                const float* __restrict__ p3w, const float* __restrict__ p3b) {
    __shared__ float pos[169 * NH_];
    int tid = threadIdx.x;
    if (tid < 169) {
        float dh = (float)(tid / 13 - 6);
        float dw = (float)(tid % 13 - 6);
        float v[24], v2[24];
        #pragma unroll
        for (int j = 0; j < 24; j++)
            v[j] = dh * ppw[j] + dw * ppw[24 + j] + ppb[j];
        dpb_layer(v, l1g, l1b, p1w, p1b, v2, 24);
        dpb_layer(v2, l2g, l2b, p2w, p2b, v, 24);
        float out12[NH_];
        dpb_layer(v, l3g, l3b, p3w, p3b, out12, NH_);
        #pragma unroll
        for (int h = 0; h < NH_; h++) pos[tid * NH_ + h] = out12[h];
    }
    __syncthreads();
    for (int e = tid; e < NH_ * N_ * N_; e += blockDim.x) {
        int h = e / (N_ * N_);
        int rem = e % (N_ * N_);
        int i = rem / N_, j = rem % N_;
        int idx = (i / G_ - j / G_ + G_ - 1) * (2 * G_ - 1) + (i % G_ - j % G_ + G_ - 1);
        g_bias[e] = pos[idx * NH_ + h];
    }
}

// ---------------- layernorm (optional window permute; bf16 output) ----------------
template<bool PERM>
__global__ void ln_kernel(const float* __restrict__ x, const float* __restrict__ g,
                          const float* __restrict__ b, bf16* __restrict__ out) {
    int t = blockIdx.x;
    const float* xr = x + (size_t)t * C_;
    int tid = threadIdx.x;
    float vals[3];
    float s = 0.f, s2 = 0.f;
    #pragma unroll
    for (int u = 0; u < 3; u++) {
        float v = xr[tid + u * 128];
        vals[u] = v; s += v; s2 += v * v;
    }
    #pragma unroll
    for (int o = 16; o; o >>= 1) {
        s  += __shfl_down_sync(0xffffffffu, s, o);
        s2 += __shfl_down_sync(0xffffffffu, s2, o);
    }
    __shared__ float shs[4], shs2[4], shm[2];
    int wid = tid >> 5, lane = tid & 31;
    if (lane == 0) { shs[wid] = s; shs2[wid] = s2; }
    __syncthreads();
    if (tid == 0) {
        float ts = shs[0] + shs[1] + shs[2] + shs[3];
        float t2 = shs2[0] + shs2[1] + shs2[2] + shs2[3];
        float mean = ts * (1.f / C_);
        float var = t2 * (1.f / C_) - mean * mean;
        shm[0] = mean;
        shm[1] = rsqrtf(var + EPS_);
    }
    __syncthreads();
    float mean = shm[0], inv = shm[1];
    bf16* orow;
    if (PERM) {
        int bb = t / (Hdim * Wdim);
        int rr = t % (Hdim * Wdim);
        int hh = rr / Wdim, ww = rr % Wdim;
        int w = bb * 16 + (hh / G_) * 4 + (ww / G_);
        int p = (hh % G_) * G_ + (ww % G_);
        orow = out + ((size_t)w * N_ + p) * C_;
    } else {
        orow = out + (size_t)t * C_;
    }
    #pragma unroll
    for (int u = 0; u < 3; u++) {
        int i = tid + u * 128;
        orow[i] = __float2bfloat16_rn((vals[u] - mean) * inv * g[i] + b[i]);
    }
}

// ---------------- bf16 mma.sync GEMM (ldmatrix fragment loads) ----------------
// C[M,Nc] = A[M,K] @ WT[Nc,K]^T + bias
// MODE 0: bf16 out          1: fp32 out, +res, window scatter
// MODE 2: bf16 out, gelu    3: fp32 out, +res
// CTA 256x128, k-chunk 64, 8 warps 4(m)x2(n), warp tile 64x64.
#define APAD 72
#define BPAD 72
#define A_BYTES (256 * APAD * 2)      // 36864
#define B_BYTES (128 * BPAD * 2)      // 18432
#define SM_BYTES (2 * (A_BYTES + B_BYTES))  // 110592

template<int MODE>
__global__ void __launch_bounds__(256, 1)
gemm_mma(const bf16* __restrict__ A, const bf16* __restrict__ WT,
         const float* __restrict__ bias, void* __restrict__ Cout,
         const float* __restrict__ res, int K, int Nc) {
    extern __shared__ __align__(16) char smem[];
    const int tid = threadIdx.x;
    const int lane = tid & 31, wid = tid >> 5;
    const int warp_m = wid & 3, warp_n = wid >> 2;
    const int m0 = blockIdx.y * 256, n0 = blockIdx.x * 128;
    const int nk = K / 64;

    uint32_t sbase = smem_u32(smem);

    auto load_chunk = [&](int kt, int buf) {
        int k0 = kt * 64;
        uint32_t sA = sbase + (buf ? A_BYTES : 0);
        uint32_t sB = sbase + 2 * A_BYTES + (buf ? B_BYTES : 0);
        #pragma unroll
        for (int u = 0; u < 8; u++) {              // 2048 cp16 = 256 rows x 64 k
            int idx = u * 256 + tid;
            int row = idx >> 3, seg = idx & 7;
            cp16(sA + (row * APAD + seg * 8) * 2,
                 &A[(size_t)(m0 + row) * K + k0 + seg * 8]);
        }
        #pragma unroll
        for (int u = 0; u < 4; u++) {              // 1024 cp16 = 128 n x 64 k
            int idx = u * 256 + tid;
            int row = idx >> 3, seg = idx & 7;
            cp16(sB + (row * BPAD + seg * 8) * 2,
                 &WT[(size_t)(n0 + row) * K + k0 + seg * 8]);
        }
        CP_COMMIT();
    };

    float acc[4][8][4];
    #pragma unroll
    for (int i = 0; i < 4; i++)
        #pragma unroll
        for (int j = 0; j < 8; j++)
            #pragma unroll
            for (int q = 0; q < 4; q++) acc[i][j][q] = 0.f;

    load_chunk(0, 0);
    load_chunk(1, 1);

    const int r = lane >> 2, cc = lane & 3;
    // ldmatrix per-lane offsets
    const int t8 = lane & 7, qg = lane >> 3;
    // A x4: matrices {rows lo/k lo, rows hi/k lo, rows lo/k hi, rows hi/k hi}
    const uint32_t a_lane_off =
        ((uint32_t)(warp_m * 64 + (qg & 1) * 8 + t8) * APAD + (qg >> 1) * 8) * 2;
    // B x4: matrices {n lo/k lo, n lo/k hi, n hi/k lo, n hi/k hi}
    const uint32_t b_lane_off =
        ((uint32_t)(warp_n * 64 + (qg >> 1) * 8 + t8) * BPAD + (qg & 1) * 8) * 2;

    for (int kt = 0; kt < nk; kt++) {
        if (kt + 1 < nk) CP_WAIT1(); else CP_WAIT0();
        __syncthreads();
        uint32_t aBuf = sbase + (kt & 1 ? A_BYTES : 0) + a_lane_off;
        uint32_t bBuf = sbase + 2 * A_BYTES + (kt & 1 ? B_BYTES : 0) + b_lane_off;
        #pragma unroll
        for (int ks = 0; ks < 4; ks++) {           // 4 x k16 = 64
            uint32_t af[4][4];
            #pragma unroll
            for (int mf = 0; mf < 4; mf++)
                ldsm4(af[mf][0], af[mf][1], af[mf][2], af[mf][3],
                      aBuf + mf * (16 * APAD * 2) + ks * 32);
            uint32_t bf[8][2];
            #pragma unroll
            for (int j = 0; j < 4; j++)
                ldsm4(bf[2*j][0], bf[2*j][1], bf[2*j+1][0], bf[2*j+1][1],
                      bBuf + j * (16 * BPAD * 2) + ks * 32);
            #pragma unroll
            for (int mf = 0; mf < 4; mf++)
                #pragma unroll
                for (int nf = 0; nf < 8; nf++)
                    mma_bf16(acc[mf][nf], af[mf][0], af[mf][1], af[mf][2], af[mf][3],
                             bf[nf][0], bf[nf][1]);
        }
        __syncthreads();
        if (kt + 2 < nk) load_chunk(kt + 2, kt & 1);
    }

    // epilogue
    #pragma unroll
    for (int mf = 0; mf < 4; mf++) {
        #pragma unroll
        for (int half = 0; half < 2; half++) {
            int row = m0 + warp_m * 64 + mf * 16 + r + half * 8;
            int orow = row;
            if (MODE == 1) {
                int w = row / N_, p = row % N_;
                int bbi = w >> 4, wi = w & 15;
                int hh = (wi >> 2) * G_ + p / G_;
                int ww = (wi & 3) * G_ + p % G_;
                orow = bbi * (Hdim * Wdim) + hh * Wdim + ww;
            }
            #pragma unroll
            for (int nf = 0; nf < 8; nf++) {
                int col = n0 + warp_n * 64 + nf * 8 + cc * 2;
                float2 bi = *(const float2*)&bias[col];
                float v0 = acc[mf][nf][half * 2 + 0] + bi.x;
                float v1 = acc[mf][nf][half * 2 + 1] + bi.y;
                if (MODE == 2) {
                    v0 = 0.5f * v0 * (1.f + erff(v0 * 0.70710678118654752f));
                    v1 = 0.5f * v1 * (1.f + erff(v1 * 0.70710678118654752f));
                }
                if (MODE == 1 || MODE == 3) {
                    float2 r2 = *(const float2*)&res[(size_t)orow * Nc + col];
                    v0 += r2.x; v1 += r2.y;
                    *(float2*)&((float*)Cout)[(size_t)orow * Nc + col] = make_float2(v0, v1);
                } else {
                    __nv_bfloat162 h2 = __floats2bfloat162_rn(v0, v1);
                    *(__nv_bfloat162*)&((bf16*)Cout)[(size_t)orow * Nc + col] = h2;
                }
            }
        }
    }
}

// ---------------- attention: one block per (window, head) ----------------
__global__ void __launch_bounds__(64) attn_kernel(const bf16* __restrict__ qkv,
                                                  bf16* __restrict__ out) {
    __shared__ float ks[N_ * 32];
    __shared__ float vs[N_ * 32];
    int w = blockIdx.x / NH_;
    int h = blockIdx.x % NH_;
    const bf16* base = qkv + (size_t)w * N_ * (3 * C_) + h * HD_;
    int tid = threadIdx.x;
    for (int e = tid; e < N_ * 4; e += 64) {
        int i = e >> 2, g = e & 3;
        uint4 ku = *(const uint4*)&base[(size_t)i * (3 * C_) + C_ + g * 8];
        uint4 vu = *(const uint4*)&base[(size_t)i * (3 * C_) + 2 * C_ + g * 8];
        float* kd = &ks[i * 32 + g * 8];
        float* vd = &vs[i * 32 + g * 8];
        kd[0] = bflo(ku.x); kd[1] = bfhi(ku.x); kd[2] = bflo(ku.y); kd[3] = bfhi(ku.y);
        kd[4] = bflo(ku.z); kd[5] = bfhi(ku.z); kd[6] = bflo(ku.w); kd[7] = bfhi(ku.w);
        vd[0] = bflo(vu.x); vd[1] = bfhi(vu.x); vd[2] = bflo(vu.y); vd[3] = bfhi(vu.y);
        vd[4] = bflo(vu.z); vd[5] = bfhi(vu.z); vd[6] = bflo(vu.w); vd[7] = bfhi(vu.w);
    }
    float q[32];
    if (tid < N_) {
        #pragma unroll
        for (int g = 0; g < 4; g++) {
            uint4 qu = *(const uint4*)&base[(size_t)tid * (3 * C_) + g * 8];
            float* qd = &q[g * 8];
            qd[0] = bflo(qu.x) * SCALE_; qd[1] = bfhi(qu.x) * SCALE_;
            qd[2] = bflo(qu.y) * SCALE_; qd[3] = bfhi(qu.y) * SCALE_;
            qd[4] = bflo(qu.z) * SCALE_; qd[5] = bfhi(qu.z) * SCALE_;
            qd[6] = bflo(qu.w) * SCALE_; qd[7] = bfhi(qu.w) * SCALE_;
        }
    }
    __syncthreads();
    if (tid >= N_) return;

    const float* bh = g_bias + h * N_ * N_ + tid * N_;
    float S[N_];
    #pragma unroll
    for (int j = 0; j < N_; j++) {
        float acc = bh[j];
        const float4* kj = (const float4*)&ks[j * 32];
        #pragma unroll
        for (int d4 = 0; d4 < 8; d4++) {
            float4 kk = kj[d4];
            acc = fmaf(q[d4*4+0], kk.x, acc);
            acc = fmaf(q[d4*4+1], kk.y, acc);
            acc = fmaf(q[d4*4+2], kk.z, acc);
            acc = fmaf(q[d4*4+3], kk.w, acc);
        }
        S[j] = acc;
    }
    float mx = S[0];
    #pragma unroll
    for (int j = 1; j < N_; j++) mx = fmaxf(mx, S[j]);
    float sum = 0.f;
    #pragma unroll
    for (int j = 0; j < N_; j++) { S[j] = __expf(S[j] - mx); sum += S[j]; }
    float inv = 1.f / sum;
    float o[32];
    #pragma unroll
    for (int d = 0; d < 32; d++) o[d] = 0.f;
    #pragma unroll
    for (int j = 0; j < N_; j++) {
        float p = S[j];
        const float4* vj = (const float4*)&vs[j * 32];
        #pragma unroll
        for (int d4 = 0; d4 < 8; d4++) {
            float4 vv = vj[d4];
            o[d4*4+0] = fmaf(p, vv.x, o[d4*4+0]);
            o[d4*4+1] = fmaf(p, vv.y, o[d4*4+1]);
            o[d4*4+2] = fmaf(p, vv.z, o[d4*4+2]);
            o[d4*4+3] = fmaf(p, vv.w, o[d4*4+3]);
        }
    }
    bf16* orow = out + (size_t)w * N_ * C_ + (size_t)tid * C_ + h * HD_;
    uint32_t st[16];
    #pragma unroll
    for (int p = 0; p < 16; p++) {
        __nv_bfloat162 h2 = __floats2bfloat162_rn(o[2*p] * inv, o[2*p+1] * inv);
        st[p] = *(uint32_t*)&h2;
    }
    #pragma unroll
    for (int g = 0; g < 4; g++)
        *(uint4*)&orow[g * 8] = make_uint4(st[4*g], st[4*g+1], st[4*g+2], st[4*g+3]);
}

// ---------------- launch ----------------
extern "C" void kernel_launch(void* const* d_in, const int* in_sizes, int n_in,
                              void* d_out, int out_size) {
    const float* x       = (const float*)d_in[0];
    const float* norm1_g = (const float*)d_in[1];
    const float* norm1_b = (const float*)d_in[2];
    const float* qkv_w   = (const float*)d_in[3];
    const float* qkv_b   = (const float*)d_in[4];
    const float* proj_w  = (const float*)d_in[5];
    const float* proj_b  = (const float*)d_in[6];
    const float* norm2_g = (const float*)d_in[7];
    const float* norm2_b = (const float*)d_in[8];
    const float* fc1_w   = (const float*)d_in[9];
    const float* fc1_b   = (const float*)d_in[10];
    const float* fc2_w   = (const float*)d_in[11];
    const float* fc2_b   = (const float*)d_in[12];
    const float* pp_w    = (const float*)d_in[13];
    const float* pp_b    = (const float*)d_in[14];
    const float* l1_g    = (const float*)d_in[15];
    const float* l1_b    = (const float*)d_in[16];
    const float* p1_w    = (const float*)d_in[17];
    const float* p1_b    = (const float*)d_in[18];
    const float* l2_g    = (const float*)d_in[19];
    const float* l2_b    = (const float*)d_in[20];
    const float* p2_w    = (const float*)d_in[21];
    const float* p2_b    = (const float*)d_in[22];
    const float* l3_g    = (const float*)d_in[23];
    const float* l3_b    = (const float*)d_in[24];
    const float* p3_w    = (const float*)d_in[25];
    const float* p3_b    = (const float*)d_in[26];
    float* out = (float*)d_out;

    bf16 *hwin, *qkvb, *attn, *h2, *mlp;
    float *x1;
    bf16 *qkvWT, *projWT, *fc1WT, *fc2WT;
    cudaGetSymbolAddress((void**)&hwin, g_hwin);
    cudaGetSymbolAddress((void**)&qkvb, g_qkv);
    cudaGetSymbolAddress((void**)&attn, g_attn);
    cudaGetSymbolAddress((void**)&x1,   g_x1);
    cudaGetSymbolAddress((void**)&h2,   g_h2);
    cudaGetSymbolAddress((void**)&mlp,  g_mlp);
    cudaGetSymbolAddress((void**)&qkvWT, g_qkvWT);
    cudaGetSymbolAddress((void**)&projWT, g_projWT);
    cudaGetSymbolAddress((void**)&fc1WT, g_fc1WT);
    cudaGetSymbolAddress((void**)&fc2WT, g_fc2WT);

    cudaFuncSetAttribute(gemm_mma<0>, cudaFuncAttributeMaxDynamicSharedMemorySize, SM_BYTES);
    cudaFuncSetAttribute(gemm_mma<1>, cudaFuncAttributeMaxDynamicSharedMemorySize, SM_BYTES);
    cudaFuncSetAttribute(gemm_mma<2>, cudaFuncAttributeMaxDynamicSharedMemorySize, SM_BYTES);
    cudaFuncSetAttribute(gemm_mma<3>, cudaFuncAttributeMaxDynamicSharedMemorySize, SM_BYTES);

    dim3 tt(32, 8);
    // weights: fp32 [K][N] -> bf16 [N][K]
    transpose_cvt<<<dim3((3*C_)/32, C_/32), tt>>>(qkv_w, qkvWT, C_, 3*C_);
    transpose_cvt<<<dim3(C_/32, C_/32), tt>>>(proj_w, projWT, C_, C_);
    transpose_cvt<<<dim3(MH_/32, C_/32), tt>>>(fc1_w, fc1WT, C_, MH_);
    transpose_cvt<<<dim3(C_/32, MH_/32), tt>>>(fc2_w, fc2WT, MH_, C_);

    pos_bias_kernel<<<1, 256>>>(pp_w, pp_b, l1_g, l1_b, p1_w, p1_b,
                                l2_g, l2_b, p2_w, p2_b, l3_g, l3_b, p3_w, p3_b);
    ln_kernel<true><<<NTOK, 128>>>(x, norm1_g, norm1_b, hwin);

    // QKV: [50176,384] x [384,1152]
    gemm_mma<0><<<dim3((3*C_)/128, NTOK/256), 256, SM_BYTES>>>(hwin, qkvWT, qkv_b, qkvb, nullptr, C_, 3*C_);
    attn_kernel<<<NWIN * NH_, 64>>>(qkvb, attn);
    // proj + residual + reverse window
    gemm_mma<1><<<dim3(C_/128, NTOK/256), 256, SM_BYTES>>>(attn, projWT, proj_b, x1, x, C_, C_);
    ln_kernel<false><<<NTOK, 128>>>(x1, norm2_g, norm2_b, h2);
    // fc1 + gelu
    gemm_mma<2><<<dim3(MH_/128, NTOK/256), 256, SM_BYTES>>>(h2, fc1WT, fc1_b, mlp, nullptr, C_, MH_);
    // fc2 + residual -> out
    gemm_mma<3><<<dim3(C_/128, NTOK/256), 256, SM_BYTES>>>(mlp, fc2WT, fc2_b, out, x1, MH_, C_);
}

// round 14
// speedup vs baseline: 5.4356x; 1.0733x over previous
#include <cuda_runtime.h>
#include <cuda_bf16.h>
#include <cstdint>
#include <math.h>

#define B_  64
#define Hdim 28
#define Wdim 28
#define C_  384
#define G_  7
#define N_  49
#define NH_ 12
#define HD_ 32
#define NTOK (B_*Hdim*Wdim)          // 50176
#define NWIN (B_*16)                 // 1024
#define SCALE_ 0.17677669529663689f
#define EPS_ 1e-5f
#define MH_ (4*C_)                   // 1536

typedef __nv_bfloat16 bf16;

// ---------------- scratch (device globals) ----------------
__device__ bf16  g_hwin[(size_t)NTOK * C_];        // LN1 out, window order
__device__ bf16  g_qkv[(size_t)NTOK * 3 * C_];     // qkv, window order
__device__ float g_bias[NH_ * N_ * N_];            // position bias [h][i][j]
__device__ bf16  g_attn[(size_t)NTOK * C_];        // attention out, window order
__device__ float g_x1[(size_t)NTOK * C_];          // x + proj (orig order, fp32)
__device__ bf16  g_h2[(size_t)NTOK * C_];          // LN2 out
__device__ bf16  g_mlp[(size_t)NTOK * MH_];        // gelu(fc1)
// bf16 transposed weights [N][K]
__device__ bf16 g_qkvWT[(size_t)(3*C_) * C_];
__device__ bf16 g_projWT[(size_t)C_ * C_];
__device__ bf16 g_fc1WT[(size_t)MH_ * C_];
__device__ bf16 g_fc2WT[(size_t)C_ * MH_];

// ---------------- helpers ----------------
__device__ __forceinline__ uint32_t smem_u32(const void* p) {
    uint32_t a;
    asm("{ .reg .u64 t; cvta.to.shared.u64 t, %1; cvt.u32.u64 %0, t; }" : "=r"(a) : "l"(p));
    return a;
}
__device__ __forceinline__ void cp16(uint32_t dst, const void* src) {
    asm volatile("cp.async.cg.shared.global [%0], [%1], 16;" :: "r"(dst), "l"(src));
}
#define CP_COMMIT() asm volatile("cp.async.commit_group;" ::: "memory")
#define CP_WAIT1()  asm volatile("cp.async.wait_group 1;" ::: "memory")
#define CP_WAIT0()  asm volatile("cp.async.wait_group 0;" ::: "memory")

__device__ __forceinline__ void mma_bf16(float* c, uint32_t a0, uint32_t a1, uint32_t a2,
                                         uint32_t a3, uint32_t b0, uint32_t b1) {
    asm volatile(
        "mma.sync.aligned.m16n8k16.row.col.f32.bf16.bf16.f32 "
        "{%0,%1,%2,%3}, {%4,%5,%6,%7}, {%8,%9}, {%0,%1,%2,%3};"
        : "+f"(c[0]), "+f"(c[1]), "+f"(c[2]), "+f"(c[3])
        : "r"(a0), "r"(a1), "r"(a2), "r"(a3), "r"(b0), "r"(b1));
}
__device__ __forceinline__ void ldsm4(uint32_t& d0, uint32_t& d1, uint32_t& d2, uint32_t& d3,
                                      uint32_t addr) {
    asm volatile("ldmatrix.sync.aligned.m8n8.x4.shared.b16 {%0,%1,%2,%3}, [%4];"
        : "=r"(d0), "=r"(d1), "=r"(d2), "=r"(d3) : "r"(addr));
}
__device__ __forceinline__ float bflo(uint32_t u) { return __uint_as_float(u << 16); }
__device__ __forceinline__ float bfhi(uint32_t u) { return __uint_as_float(u & 0xFFFF0000u); }

// ---------------- weight convert+transpose: fp32 [R][Cc] -> bf16 [Cc][R] ----------------
__global__ void transpose_cvt(const float* __restrict__ in, bf16* __restrict__ out,
                              int R, int Cc) {
    __shared__ float t[32][33];
    int bx = blockIdx.x * 32, by = blockIdx.y * 32;
    int x = bx + threadIdx.x;
    #pragma unroll
    for (int u = 0; u < 32; u += 8) {
        int y = by + threadIdx.y + u;
        t[threadIdx.y + u][threadIdx.x] = in[(size_t)y * Cc + x];
    }
    __syncthreads();
    x = by + threadIdx.x;
    #pragma unroll
    for (int u = 0; u < 32; u += 8) {
        int y = bx + threadIdx.y + u;
        out[(size_t)y * R + x] = __float2bfloat16_rn(t[threadIdx.x][threadIdx.y + u]);
    }
}

// ---------------- dynamic position bias ----------------
__device__ __forceinline__ void dpb_layer(const float* v, const float* g, const float* b,
                                          const float* w, const float* bias,
                                          float* out, int outdim) {
    float m = 0.f;
    #pragma unroll
    for (int j = 0; j < 24; j++) m += v[j];
    m *= (1.f / 24.f);
    float var = 0.f;
    #pragma unroll
    for (int j = 0; j < 24; j++) { float d = v[j] - m; var += d * d; }
    var *= (1.f / 24.f);
    float inv = rsqrtf(var + EPS_);
    float t[24];
    #pragma unroll
    for (int j = 0; j < 24; j++)
        t[j] = fmaxf((v[j] - m) * inv * g[j] + b[j], 0.f);
    for (int o = 0; o < outdim; o++) {
        float s = bias[o];
        #pragma unroll
        for (int i = 0; i < 24; i++) s += t[i] * w[i * outdim + o];
        out[o] = s;
    }
}

__global__ void pos_bias_kernel(const float* __restrict__ ppw, const float* __restrict__ ppb,
                                const float* __restrict__ l1g, const float* __restrict__ l1b,
                                const float* __restrict__ p1w, const float* __restrict__ p1b,
                                const float* __restrict__ l2g, const float* __restrict__ l2b,
                                const float* __restrict__ p2w, const float* __restrict__ p2b,
                                const float* __restrict__ l3g, const float* __restrict__ l3b,
                                const float* __restrict__ p3w, const float* __restrict__ p3b) {
    __shared__ float pos[169 * NH_];
    int tid = threadIdx.x;
    if (tid < 169) {
        float dh = (float)(tid / 13 - 6);
        float dw = (float)(tid % 13 - 6);
        float v[24], v2[24];
        #pragma unroll
        for (int j = 0; j < 24; j++)
            v[j] = dh * ppw[j] + dw * ppw[24 + j] + ppb[j];
        dpb_layer(v, l1g, l1b, p1w, p1b, v2, 24);
        dpb_layer(v2, l2g, l2b, p2w, p2b, v, 24);
        float out12[NH_];
        dpb_layer(v, l3g, l3b, p3w, p3b, out12, NH_);
        #pragma unroll
        for (int h = 0; h < NH_; h++) pos[tid * NH_ + h] = out12[h];
    }
    __syncthreads();
    for (int e = tid; e < NH_ * N_ * N_; e += blockDim.x) {
        int h = e / (N_ * N_);
        int rem = e % (N_ * N_);
        int i = rem / N_, j = rem % N_;
        int idx = (i / G_ - j / G_ + G_ - 1) * (2 * G_ - 1) + (i % G_ - j % G_ + G_ - 1);
        g_bias[e] = pos[idx * NH_ + h];
    }
}

// ---------------- layernorm (optional window permute; bf16 output) ----------------
template<bool PERM>
__global__ void ln_kernel(const float* __restrict__ x, const float* __restrict__ g,
                          const float* __restrict__ b, bf16* __restrict__ out) {
    int t = blockIdx.x;
    const float* xr = x + (size_t)t * C_;
    int tid = threadIdx.x;
    float vals[3];
    float s = 0.f, s2 = 0.f;
    #pragma unroll
    for (int u = 0; u < 3; u++) {
        float v = xr[tid + u * 128];
        vals[u] = v; s += v; s2 += v * v;
    }
    #pragma unroll
    for (int o = 16; o; o >>= 1) {
        s  += __shfl_down_sync(0xffffffffu, s, o);
        s2 += __shfl_down_sync(0xffffffffu, s2, o);
    }
    __shared__ float shs[4], shs2[4], shm[2];
    int wid = tid >> 5, lane = tid & 31;
    if (lane == 0) { shs[wid] = s; shs2[wid] = s2; }
    __syncthreads();
    if (tid == 0) {
        float ts = shs[0] + shs[1] + shs[2] + shs[3];
        float t2 = shs2[0] + shs2[1] + shs2[2] + shs2[3];
        float mean = ts * (1.f / C_);
        float var = t2 * (1.f / C_) - mean * mean;
        shm[0] = mean;
        shm[1] = rsqrtf(var + EPS_);
    }
    __syncthreads();
    float mean = shm[0], inv = shm[1];
    bf16* orow;
    if (PERM) {
        int bb = t / (Hdim * Wdim);
        int rr = t % (Hdim * Wdim);
        int hh = rr / Wdim, ww = rr % Wdim;
        int w = bb * 16 + (hh / G_) * 4 + (ww / G_);
        int p = (hh % G_) * G_ + (ww % G_);
        orow = out + ((size_t)w * N_ + p) * C_;
    } else {
        orow = out + (size_t)t * C_;
    }
    #pragma unroll
    for (int u = 0; u < 3; u++) {
        int i = tid + u * 128;
        orow[i] = __float2bfloat16_rn((vals[u] - mean) * inv * g[i] + b[i]);
    }
}

// ---------------- bf16 mma.sync GEMM (ldmatrix, 128x128 tile, 2 CTAs/SM) ----------------
// C[M,Nc] = A[M,K] @ WT[Nc,K]^T + bias
// MODE 0: bf16 out          1: fp32 out, +res, window scatter
// MODE 2: bf16 out, gelu    3: fp32 out, +res
// CTA 128x128, k-chunk 64, 8 warps 4(m)x2(n), warp tile 32x64.
#define APAD 72
#define BPAD 72
#define A_BYTES (128 * APAD * 2)      // 18432
#define B_BYTES (128 * BPAD * 2)      // 18432
#define SM_BYTES (2 * (A_BYTES + B_BYTES))  // 73728

template<int MODE>
__global__ void __launch_bounds__(256, 2)
gemm_mma(const bf16* __restrict__ A, const bf16* __restrict__ WT,
         const float* __restrict__ bias, void* __restrict__ Cout,
         const float* __restrict__ res, int K, int Nc) {
    extern __shared__ __align__(16) char smem[];
    const int tid = threadIdx.x;
    const int lane = tid & 31, wid = tid >> 5;
    const int warp_m = wid & 3, warp_n = wid >> 2;
    const int m0 = blockIdx.y * 128, n0 = blockIdx.x * 128;
    const int nk = K / 64;

    uint32_t sbase = smem_u32(smem);

    auto load_chunk = [&](int kt, int buf) {
        int k0 = kt * 64;
        uint32_t sA = sbase + (buf ? A_BYTES : 0);
        uint32_t sB = sbase + 2 * A_BYTES + (buf ? B_BYTES : 0);
        #pragma unroll
        for (int u = 0; u < 4; u++) {              // 1024 cp16 = 128 rows x 64 k
            int idx = u * 256 + tid;
            int row = idx >> 3, seg = idx & 7;
            cp16(sA + (row * APAD + seg * 8) * 2,
                 &A[(size_t)(m0 + row) * K + k0 + seg * 8]);
        }
        #pragma unroll
        for (int u = 0; u < 4; u++) {              // 1024 cp16 = 128 n x 64 k
            int idx = u * 256 + tid;
            int row = idx >> 3, seg = idx & 7;
            cp16(sB + (row * BPAD + seg * 8) * 2,
                 &WT[(size_t)(n0 + row) * K + k0 + seg * 8]);
        }
        CP_COMMIT();
    };

    float acc[2][8][4];
    #pragma unroll
    for (int i = 0; i < 2; i++)
        #pragma unroll
        for (int j = 0; j < 8; j++)
            #pragma unroll
            for (int q = 0; q < 4; q++) acc[i][j][q] = 0.f;

    load_chunk(0, 0);
    load_chunk(1, 1);

    const int r = lane >> 2, cc = lane & 3;
    const int t8 = lane & 7, qg = lane >> 3;
    // A x4: matrices {rows lo/k lo, rows hi/k lo, rows lo/k hi, rows hi/k hi}
    const uint32_t a_lane_off =
        ((uint32_t)(warp_m * 32 + (qg & 1) * 8 + t8) * APAD + (qg >> 1) * 8) * 2;
    // B x4: matrices {n lo/k lo, n lo/k hi, n hi/k lo, n hi/k hi}
    const uint32_t b_lane_off =
        ((uint32_t)(warp_n * 64 + (qg >> 1) * 8 + t8) * BPAD + (qg & 1) * 8) * 2;

    for (int kt = 0; kt < nk; kt++) {
        if (kt + 1 < nk) CP_WAIT1(); else CP_WAIT0();
        __syncthreads();
        uint32_t aBuf = sbase + (kt & 1 ? A_BYTES : 0) + a_lane_off;
        uint32_t bBuf = sbase + 2 * A_BYTES + (kt & 1 ? B_BYTES : 0) + b_lane_off;
        #pragma unroll
        for (int ks = 0; ks < 4; ks++) {           // 4 x k16 = 64
            uint32_t af[2][4];
            #pragma unroll
            for (int mf = 0; mf < 2; mf++)
                ldsm4(af[mf][0], af[mf][1], af[mf][2], af[mf][3],
                      aBuf + mf * (16 * APAD * 2) + ks * 32);
            uint32_t bf[8][2];
            #pragma unroll
            for (int j = 0; j < 4; j++)
                ldsm4(bf[2*j][0], bf[2*j][1], bf[2*j+1][0], bf[2*j+1][1],
                      bBuf + j * (16 * BPAD * 2) + ks * 32);
            #pragma unroll
            for (int mf = 0; mf < 2; mf++)
                #pragma unroll
                for (int nf = 0; nf < 8; nf++)
                    mma_bf16(acc[mf][nf], af[mf][0], af[mf][1], af[mf][2], af[mf][3],
                             bf[nf][0], bf[nf][1]);
        }
        __syncthreads();
        if (kt + 2 < nk) load_chunk(kt + 2, kt & 1);
    }

    // epilogue
    #pragma unroll
    for (int mf = 0; mf < 2; mf++) {
        #pragma unroll
        for (int half = 0; half < 2; half++) {
            int row = m0 + warp_m * 32 + mf * 16 + r + half * 8;
            int orow = row;
            if (MODE == 1) {
                int w = row / N_, p = row % N_;
                int bbi = w >> 4, wi = w & 15;
                int hh = (wi >> 2) * G_ + p / G_;
                int ww = (wi & 3) * G_ + p % G_;
                orow = bbi * (Hdim * Wdim) + hh * Wdim + ww;
            }
            #pragma unroll
            for (int nf = 0; nf < 8; nf++) {
                int col = n0 + warp_n * 64 + nf * 8 + cc * 2;
                float2 bi = *(const float2*)&bias[col];
                float v0 = acc[mf][nf][half * 2 + 0] + bi.x;
                float v1 = acc[mf][nf][half * 2 + 1] + bi.y;
                if (MODE == 2) {
                    v0 = 0.5f * v0 * (1.f + erff(v0 * 0.70710678118654752f));
                    v1 = 0.5f * v1 * (1.f + erff(v1 * 0.70710678118654752f));
                }
                if (MODE == 1 || MODE == 3) {
                    float2 r2 = *(const float2*)&res[(size_t)orow * Nc + col];
                    v0 += r2.x; v1 += r2.y;
                    *(float2*)&((float*)Cout)[(size_t)orow * Nc + col] = make_float2(v0, v1);
                } else {
                    __nv_bfloat162 h2 = __floats2bfloat162_rn(v0, v1);
                    *(__nv_bfloat162*)&((bf16*)Cout)[(size_t)orow * Nc + col] = h2;
                }
            }
        }
    }
}

// ---------------- attention: one block per (window, head) ----------------
__global__ void __launch_bounds__(64) attn_kernel(const bf16* __restrict__ qkv,
                                                  bf16* __restrict__ out) {
    __shared__ float ks[N_ * 32];
    __shared__ float vs[N_ * 32];
    int w = blockIdx.x / NH_;
    int h = blockIdx.x % NH_;
    const bf16* base = qkv + (size_t)w * N_ * (3 * C_) + h * HD_;
    int tid = threadIdx.x;
    for (int e = tid; e < N_ * 4; e += 64) {
        int i = e >> 2, g = e & 3;
        uint4 ku = *(const uint4*)&base[(size_t)i * (3 * C_) + C_ + g * 8];
        uint4 vu = *(const uint4*)&base[(size_t)i * (3 * C_) + 2 * C_ + g * 8];
        float* kd = &ks[i * 32 + g * 8];
        float* vd = &vs[i * 32 + g * 8];
        kd[0] = bflo(ku.x); kd[1] = bfhi(ku.x); kd[2] = bflo(ku.y); kd[3] = bfhi(ku.y);
        kd[4] = bflo(ku.z); kd[5] = bfhi(ku.z); kd[6] = bflo(ku.w); kd[7] = bfhi(ku.w);
        vd[0] = bflo(vu.x); vd[1] = bfhi(vu.x); vd[2] = bflo(vu.y); vd[3] = bfhi(vu.y);
        vd[4] = bflo(vu.z); vd[5] = bfhi(vu.z); vd[6] = bflo(vu.w); vd[7] = bfhi(vu.w);
    }
    float q[32];
    if (tid < N_) {
        #pragma unroll
        for (int g = 0; g < 4; g++) {
            uint4 qu = *(const uint4*)&base[(size_t)tid * (3 * C_) + g * 8];
            float* qd = &q[g * 8];
            qd[0] = bflo(qu.x) * SCALE_; qd[1] = bfhi(qu.x) * SCALE_;
            qd[2] = bflo(qu.y) * SCALE_; qd[3] = bfhi(qu.y) * SCALE_;
            qd[4] = bflo(qu.z) * SCALE_; qd[5] = bfhi(qu.z) * SCALE_;
            qd[6] = bflo(qu.w) * SCALE_; qd[7] = bfhi(qu.w) * SCALE_;
        }
    }
    __syncthreads();
    if (tid >= N_) return;

    const float* bh = g_bias + h * N_ * N_ + tid * N_;
    float S[N_];
    #pragma unroll
    for (int j = 0; j < N_; j++) {
        float acc = bh[j];
        const float4* kj = (const float4*)&ks[j * 32];
        #pragma unroll
        for (int d4 = 0; d4 < 8; d4++) {
            float4 kk = kj[d4];
            acc = fmaf(q[d4*4+0], kk.x, acc);
            acc = fmaf(q[d4*4+1], kk.y, acc);
            acc = fmaf(q[d4*4+2], kk.z, acc);
            acc = fmaf(q[d4*4+3], kk.w, acc);
        }
        S[j] = acc;
    }
    float mx = S[0];
    #pragma unroll
    for (int j = 1; j < N_; j++) mx = fmaxf(mx, S[j]);
    float sum = 0.f;
    #pragma unroll
    for (int j = 0; j < N_; j++) { S[j] = __expf(S[j] - mx); sum += S[j]; }
    float inv = 1.f / sum;
    float o[32];
    #pragma unroll
    for (int d = 0; d < 32; d++) o[d] = 0.f;
    #pragma unroll
    for (int j = 0; j < N_; j++) {
        float p = S[j];
        const float4* vj = (const float4*)&vs[j * 32];
        #pragma unroll
        for (int d4 = 0; d4 < 8; d4++) {
            float4 vv = vj[d4];
            o[d4*4+0] = fmaf(p, vv.x, o[d4*4+0]);
            o[d4*4+1] = fmaf(p, vv.y, o[d4*4+1]);
            o[d4*4+2] = fmaf(p, vv.z, o[d4*4+2]);
            o[d4*4+3] = fmaf(p, vv.w, o[d4*4+3]);
        }
    }
    bf16* orow = out + (size_t)w * N_ * C_ + (size_t)tid * C_ + h * HD_;
    uint32_t st[16];
    #pragma unroll
    for (int p = 0; p < 16; p++) {
        __nv_bfloat162 h2 = __floats2bfloat162_rn(o[2*p] * inv, o[2*p+1] * inv);
        st[p] = *(uint32_t*)&h2;
    }
    #pragma unroll
    for (int g = 0; g < 4; g++)
        *(uint4*)&orow[g * 8] = make_uint4(st[4*g], st[4*g+1], st[4*g+2], st[4*g+3]);
}

// ---------------- launch ----------------
extern "C" void kernel_launch(void* const* d_in, const int* in_sizes, int n_in,
                              void* d_out, int out_size) {
    const float* x       = (const float*)d_in[0];
    const float* norm1_g = (const float*)d_in[1];
    const float* norm1_b = (const float*)d_in[2];
    const float* qkv_w   = (const float*)d_in[3];
    const float* qkv_b   = (const float*)d_in[4];
    const float* proj_w  = (const float*)d_in[5];
    const float* proj_b  = (const float*)d_in[6];
    const float* norm2_g = (const float*)d_in[7];
    const float* norm2_b = (const float*)d_in[8];
    const float* fc1_w   = (const float*)d_in[9];
    const float* fc1_b   = (const float*)d_in[10];
    const float* fc2_w   = (const float*)d_in[11];
    const float* fc2_b   = (const float*)d_in[12];
    const float* pp_w    = (const float*)d_in[13];
    const float* pp_b    = (const float*)d_in[14];
    const float* l1_g    = (const float*)d_in[15];
    const float* l1_b    = (const float*)d_in[16];
    const float* p1_w    = (const float*)d_in[17];
    const float* p1_b    = (const float*)d_in[18];
    const float* l2_g    = (const float*)d_in[19];
    const float* l2_b    = (const float*)d_in[20];
    const float* p2_w    = (const float*)d_in[21];
    const float* p2_b    = (const float*)d_in[22];
    const float* l3_g    = (const float*)d_in[23];
    const float* l3_b    = (const float*)d_in[24];
    const float* p3_w    = (const float*)d_in[25];
    const float* p3_b    = (const float*)d_in[26];
    float* out = (float*)d_out;

    bf16 *hwin, *qkvb, *attn, *h2, *mlp;
    float *x1;
    bf16 *qkvWT, *projWT, *fc1WT, *fc2WT;
    cudaGetSymbolAddress((void**)&hwin, g_hwin);
    cudaGetSymbolAddress((void**)&qkvb, g_qkv);
    cudaGetSymbolAddress((void**)&attn, g_attn);
    cudaGetSymbolAddress((void**)&x1,   g_x1);
    cudaGetSymbolAddress((void**)&h2,   g_h2);
    cudaGetSymbolAddress((void**)&mlp,  g_mlp);
    cudaGetSymbolAddress((void**)&qkvWT, g_qkvWT);
    cudaGetSymbolAddress((void**)&projWT, g_projWT);
    cudaGetSymbolAddress((void**)&fc1WT, g_fc1WT);
    cudaGetSymbolAddress((void**)&fc2WT, g_fc2WT);

    cudaFuncSetAttribute(gemm_mma<0>, cudaFuncAttributeMaxDynamicSharedMemorySize, SM_BYTES);
    cudaFuncSetAttribute(gemm_mma<1>, cudaFuncAttributeMaxDynamicSharedMemorySize, SM_BYTES);
    cudaFuncSetAttribute(gemm_mma<2>, cudaFuncAttributeMaxDynamicSharedMemorySize, SM_BYTES);
    cudaFuncSetAttribute(gemm_mma<3>, cudaFuncAttributeMaxDynamicSharedMemorySize, SM_BYTES);

    dim3 tt(32, 8);
    // weights: fp32 [K][N] -> bf16 [N][K]
    transpose_cvt<<<dim3((3*C_)/32, C_/32), tt>>>(qkv_w, qkvWT, C_, 3*C_);
    transpose_cvt<<<dim3(C_/32, C_/32), tt>>>(proj_w, projWT, C_, C_);
    transpose_cvt<<<dim3(MH_/32, C_/32), tt>>>(fc1_w, fc1WT, C_, MH_);
    transpose_cvt<<<dim3(C_/32, MH_/32), tt>>>(fc2_w, fc2WT, MH_, C_);

    pos_bias_kernel<<<1, 256>>>(pp_w, pp_b, l1_g, l1_b, p1_w, p1_b,
                                l2_g, l2_b, p2_w, p2_b, l3_g, l3_b, p3_w, p3_b);
    ln_kernel<true><<<NTOK, 128>>>(x, norm1_g, norm1_b, hwin);

    // QKV: [50176,384] x [384,1152]
    gemm_mma<0><<<dim3((3*C_)/128, NTOK/128), 256, SM_BYTES>>>(hwin, qkvWT, qkv_b, qkvb, nullptr, C_, 3*C_);
    attn_kernel<<<NWIN * NH_, 64>>>(qkvb, attn);
    // proj + residual + reverse window
    gemm_mma<1><<<dim3(C_/128, NTOK/128), 256, SM_BYTES>>>(attn, projWT, proj_b, x1, x, C_, C_);
    ln_kernel<false><<<NTOK, 128>>>(x1, norm2_g, norm2_b, h2);
    // fc1 + gelu
    gemm_mma<2><<<dim3(MH_/128, NTOK/128), 256, SM_BYTES>>>(h2, fc1WT, fc1_b, mlp, nullptr, C_, MH_);
    // fc2 + residual -> out
    gemm_mma<3><<<dim3(C_/128, NTOK/128), 256, SM_BYTES>>>(mlp, fc2WT, fc2_b, out, x1, MH_, C_);
}